// round 15
// baseline (speedup 1.0000x reference)
#include <cuda_runtime.h>
#include <cuda_fp16.h>
#include <cstdint>
#include <cstddef>

#define B_  32
#define L_  512
#define E_  768
#define F_  512
#define M_  (B_ * L_)
#define EPSF 1e-7f

#define OFF_APRED 0L
#define OFF_OPRED 49152L
#define OFF_SPRED 98304L
#define OFF_AINT  147456L
#define OFF_OINT  16924672L
#define OFF_CINT  33701888L
#define OFF_CCONV 46284800L

__device__ __half g_ah  [(size_t)M_ * E_];
__device__ __half g_oh  [(size_t)M_ * E_];
__device__ __half g_ch  [(size_t)M_ * E_];
__device__ __half g_cqh [(size_t)M_ * E_];
__device__ __half g_posh[(size_t)B_ * L_ * L_];
__device__ __half g_Wah [2304 * 512];
__device__ __half g_Woh [2304 * 512];
__device__ __half g_Wch [2304 * 768];
__device__ __half g_aconvh[(size_t)M_ * F_];
__device__ __half g_oconvh[(size_t)M_ * F_];
__device__ __half g_cconvh[(size_t)M_ * E_];
__device__ __half g_cconvn[(size_t)M_ * E_];
__device__ __half g_T1h[(size_t)B_ * L_ * E_];
__device__ __half g_A1h[(size_t)B_ * L_ * L_];
__device__ __half g_A2h[(size_t)B_ * L_ * L_];
__device__ __half g_WAh[(size_t)B_ * L_ * L_];
__device__ float g_G [(size_t)B_ * L_ * L_];   // first half reused as fp16 expG
__device__ float g_WA[(size_t)B_ * L_ * L_];
__device__ float g_inva[M_], g_invo[M_], g_invc[M_];
__device__ float g_rowsum[M_], g_colsum[M_], g_colsumP[M_];
__device__ float g_msum[B_];
__device__ float g_conf[M_];
__device__ float g_q[(size_t)B_ * E_];
__device__ float g_P1 [(size_t)M_ * 3];
__device__ float g_P1a[(size_t)M_ * 3];
__device__ float g_Ps [(size_t)M_ * 3];
__device__ float g_qs [B_ * 3];

// ---------------- helpers ----------------
__device__ __forceinline__ uint32_t su32(const void* p) {
    uint32_t a;
    asm("{ .reg .u64 t; cvta.to.shared.u64 t, %1; cvt.u32.u64 %0, t; }" : "=r"(a) : "l"(p));
    return a;
}
__device__ __forceinline__ void ldm_x4(uint32_t* r, uint32_t addr) {
    asm volatile("ldmatrix.sync.aligned.m8n8.x4.shared.b16 {%0,%1,%2,%3}, [%4];"
                 : "=r"(r[0]), "=r"(r[1]), "=r"(r[2]), "=r"(r[3]) : "r"(addr));
}
__device__ __forceinline__ void ldm_x4t(uint32_t* r, uint32_t addr) {
    asm volatile("ldmatrix.sync.aligned.m8n8.x4.trans.shared.b16 {%0,%1,%2,%3}, [%4];"
                 : "=r"(r[0]), "=r"(r[1]), "=r"(r[2]), "=r"(r[3]) : "r"(addr));
}
__device__ __forceinline__ void mma_f16(float* c, const uint32_t* a, const uint32_t* b) {
    asm volatile(
        "mma.sync.aligned.m16n8k16.row.col.f32.f16.f16.f32 "
        "{%0,%1,%2,%3}, {%4,%5,%6,%7}, {%8,%9}, {%0,%1,%2,%3};"
        : "+f"(c[0]), "+f"(c[1]), "+f"(c[2]), "+f"(c[3])
        : "r"(a[0]), "r"(a[1]), "r"(a[2]), "r"(a[3]), "r"(b[0]), "r"(b[1]));
}
__device__ __forceinline__ uint32_t pkh(float x, float y) {
    __half2 t = __floats2half2_rn(x, y);
    return *reinterpret_cast<uint32_t*>(&t);
}

// ---------------- fp16 tensor-core GEMM, BK=64, one barrier/chunk ----------------
// Modes: NT (B [N,K]); BNN (B [K,N], trans ldm); ATN (A [K,M], trans ldm).
#define AROWB 144
#define NROWB 272
#define S_B   18432
#define STAGE 36864
#define SMEM_DYN (2 * STAGE)

template<bool GATHER, bool BNN, bool ATN>
__global__ __launch_bounds__(256, 2)
void tc_gemm(const __half* __restrict__ A, long long ab, int lda,
             const __half* __restrict__ Bm, long long bb, int ldb, int K,
             float* __restrict__ C, long long cb, int ldc,
             const float* __restrict__ bias,
             const float* __restrict__ rs, const float* __restrict__ cs,
             const float* __restrict__ addp,
             const float* __restrict__ rowv, const float* __restrict__ colv,
             float* __restrict__ C2, int ldc2,
             __half* __restrict__ Ch, long long cbh, int ldch,
             int doexp)
{
    extern __shared__ char smem[];
    const int tid = threadIdx.x;
    const int lane = tid & 31, wid = tid >> 5;
    const int wm = wid & 3, wn = wid >> 2;
    const int m0 = blockIdx.x * 128, n0 = blockIdx.y * 128, bz = blockIdx.z;
    const uint32_t sb0 = su32(smem);

    const __half* Ab = GATHER ? A : (A + (size_t)bz * ab);
    const __half* Bb = Bm + (size_t)bz * bb;

    float c[2][8][4];
#pragma unroll
    for (int i = 0; i < 2; i++)
#pragma unroll
        for (int j = 0; j < 8; j++)
#pragma unroll
            for (int k = 0; k < 4; k++) c[i][j][k] = 0.f;

    const int nch = K / 64;
    uint4 va[4], vb[4];

    auto ldg = [&](int kc) {
        const int k0 = kc * 64;
        if (ATN) {
#pragma unroll
            for (int p = 0; p < 4; p++) {
                const int idx = tid + p * 256, kr = idx >> 4, c16 = idx & 15;
                va[p] = *reinterpret_cast<const uint4*>(Ab + (size_t)(k0 + kr) * lda + m0 + c16 * 8);
            }
        } else {
#pragma unroll
            for (int p = 0; p < 4; p++) {
                const int idx = tid + p * 256, row = idx >> 3, c16 = idx & 7;
                if (GATHER) {
                    const int gm = m0 + row, b = gm >> 9, l = gm & 511;
                    const int tap = kc / 12, e0 = (kc - tap * 12) * 64;
                    const int src = l + tap - 1;
                    va[p] = ((unsigned)src < 512u)
                        ? *reinterpret_cast<const uint4*>(A + ((size_t)(b * 512 + src)) * 768 + e0 + c16 * 8)
                        : make_uint4(0u, 0u, 0u, 0u);
                } else {
                    va[p] = *reinterpret_cast<const uint4*>(Ab + (size_t)(m0 + row) * lda + k0 + c16 * 8);
                }
            }
        }
        if (BNN) {
#pragma unroll
            for (int p = 0; p < 4; p++) {
                const int idx = tid + p * 256, kr = idx >> 4, c16 = idx & 15;
                vb[p] = *reinterpret_cast<const uint4*>(Bb + (size_t)(k0 + kr) * ldb + n0 + c16 * 8);
            }
        } else {
#pragma unroll
            for (int p = 0; p < 4; p++) {
                const int idx = tid + p * 256, row = idx >> 3, c16 = idx & 7;
                vb[p] = *reinterpret_cast<const uint4*>(Bb + (size_t)(n0 + row) * ldb + k0 + c16 * 8);
            }
        }
    };
    auto sts = [&](int s) {
        char* sp = smem + s * STAGE;
        if (ATN) {
#pragma unroll
            for (int p = 0; p < 4; p++) {
                const int idx = tid + p * 256, kr = idx >> 4, c16 = idx & 15;
                *reinterpret_cast<uint4*>(sp + kr * NROWB + c16 * 16) = va[p];
            }
        } else {
#pragma unroll
            for (int p = 0; p < 4; p++) {
                const int idx = tid + p * 256, row = idx >> 3, c16 = idx & 7;
                *reinterpret_cast<uint4*>(sp + row * AROWB + c16 * 16) = va[p];
            }
        }
        if (BNN) {
#pragma unroll
            for (int p = 0; p < 4; p++) {
                const int idx = tid + p * 256, kr = idx >> 4, c16 = idx & 15;
                *reinterpret_cast<uint4*>(sp + S_B + kr * NROWB + c16 * 16) = vb[p];
            }
        } else {
#pragma unroll
            for (int p = 0; p < 4; p++) {
                const int idx = tid + p * 256, row = idx >> 3, c16 = idx & 7;
                *reinterpret_cast<uint4*>(sp + S_B + row * AROWB + c16 * 16) = vb[p];
            }
        }
    };

    const uint32_t a_lrow = (lane & 15), a_lcol = (lane >> 4) * 8;
    const uint32_t atn_krow = (lane & 7) + ((lane >> 4) << 3), atn_mcol = ((lane >> 3) & 1) * 8;
    const uint32_t nt_lrow = (lane & 7) + ((lane >> 4) << 3), nt_lcol = ((lane >> 3) & 1) * 8;
    const uint32_t nn_krow = (lane & 7) + (((lane >> 3) & 1) << 3), nn_ncol = (lane >> 4) * 8;

    auto compute = [&](int s) {
        const uint32_t base = sb0 + s * STAGE;
#pragma unroll
        for (int ks = 0; ks < 4; ks++) {
            const int kk = ks * 16;
            uint32_t af[2][4];
#pragma unroll
            for (int mf = 0; mf < 2; mf++) {
                if (ATN)
                    ldm_x4t(af[mf], base + (kk + atn_krow) * NROWB + (wm * 32 + mf * 16 + atn_mcol) * 2);
                else
                    ldm_x4(af[mf], base + (wm * 32 + mf * 16 + a_lrow) * AROWB + (kk + a_lcol) * 2);
            }
#pragma unroll
            for (int nf2 = 0; nf2 < 4; nf2++) {
                uint32_t bt[4];
                if (BNN)
                    ldm_x4t(bt, base + S_B + (kk + nn_krow) * NROWB + (wn * 64 + nf2 * 16 + nn_ncol) * 2);
                else
                    ldm_x4(bt, base + S_B + (wn * 64 + nf2 * 16 + nt_lrow) * AROWB + (kk + nt_lcol) * 2);
#pragma unroll
                for (int mf = 0; mf < 2; mf++) {
                    mma_f16(c[mf][nf2 * 2 + 0], af[mf], bt);
                    mma_f16(c[mf][nf2 * 2 + 1], af[mf], bt + 2);
                }
            }
        }
    };

    ldg(0);
    sts(0);
    ldg(1);
    __syncthreads();
    for (int i = 0; i < nch; i++) {
        if (i + 1 < nch) sts((i + 1) & 1);
        if (i + 2 < nch) ldg(i + 2);
        compute(i & 1);
        __syncthreads();
    }

    const int tm = lane >> 2, tn = (lane & 3) * 2;
#pragma unroll
    for (int mf = 0; mf < 2; mf++) {
#pragma unroll
        for (int nf = 0; nf < 8; nf++) {
#pragma unroll
            for (int half = 0; half < 2; half++) {
                const int m = m0 + wm * 32 + mf * 16 + tm + half * 8;
                const int nn = n0 + wn * 64 + nf * 8 + tn;
                float v0 = c[mf][nf][half * 2 + 0];
                float v1 = c[mf][nf][half * 2 + 1];
                if (rs) { const float r = rs[bz * 512 + m]; v0 *= r; v1 *= r; }
                if (cs) { v0 *= cs[bz * 512 + nn]; v1 *= cs[bz * 512 + nn + 1]; }
                if (doexp) { v0 = expf(v0); v1 = expf(v1); }
                if (bias) {
                    v0 = fmaxf(v0 + bias[nn], 0.f);
                    v1 = fmaxf(v1 + bias[nn + 1], 0.f);
                }
                if (C) {
                    const size_t rowoff = (size_t)bz * cb + (size_t)m * ldc + nn;
                    if (addp) { v0 += addp[rowoff]; v1 += addp[rowoff + 1]; }
                    if (rowv) {
                        const float rv = rowv[bz * 512 + m];
                        v0 += rv * colv[(size_t)bz * ldc + nn];
                        v1 += rv * colv[(size_t)bz * ldc + nn + 1];
                    }
                    C[rowoff] = v0; C[rowoff + 1] = v1;
                }
                if (C2) {
                    float* c2 = C2 + (size_t)m * ldc2 + nn;
                    c2[0] = v0; c2[1] = v1;
                }
                if (Ch) {
                    *reinterpret_cast<__half2*>(Ch + (size_t)bz * cbh + (size_t)m * ldch + nn) =
                        __floats2half2_rn(v0, v1);
                }
            }
        }
    }
}

// ---------------- small kernels ----------------
__global__ void cvt_k(const float4* __restrict__ src, uint2* __restrict__ dst, int n4)
{
    const int i = blockIdx.x * 256 + threadIdx.x;
    if (i < n4) {
        float4 v = src[i];
        dst[i] = make_uint2(pkh(v.x, v.y), pkh(v.z, v.w));
    }
}
// cconvn[j,e] = cconvh[j,e] * invc[j]
__global__ void scalec_k()
{
    const int i = blockIdx.x * 256 + threadIdx.x;   // half2 index
    if (i < M_ * 384) {
        const int row = i / 384;
        float2 v = __half22float2(reinterpret_cast<const __half2*>(g_cconvh)[i]);
        const float s = g_invc[row];
        reinterpret_cast<__half2*>(g_cconvn)[i] = __floats2half2_rn(v.x * s, v.y * s);
    }
}
__global__ void rowinv_h(const __half* __restrict__ X, int D, float* __restrict__ inv)
{
    const int m = blockIdx.x, t = threadIdx.x;
    float s = 0.f;
    const __half2* xr = reinterpret_cast<const __half2*>(X + (size_t)m * D);
    for (int k = t; k < D / 2; k += 256) {
        float2 v = __half22float2(xr[k]);
        s = fmaf(v.x, v.x, fmaf(v.y, v.y, s));
    }
    __shared__ float red[256];
    red[t] = s; __syncthreads();
    for (int st = 128; st > 0; st >>= 1) { if (t < st) red[t] += red[t + st]; __syncthreads(); }
    if (t == 0) inv[m] = rsqrtf(fmaxf(red[0], 1e-12f));
}
__global__ void rowsum_k(const float* __restrict__ mask)
{
    const __half* eG = reinterpret_cast<const __half*>(g_G);
    const int row = blockIdx.x, t = threadIdx.x;
    const int b = row >> 9;
    float v = __half2float(eG[(size_t)row * L_ + t]) * mask[b * L_ + t];
    __shared__ float red[512];
    red[t] = v; __syncthreads();
    for (int st = 256; st > 0; st >>= 1) { if (t < st) red[t] += red[t + st]; __syncthreads(); }
    if (t == 0) g_rowsum[row] = red[0];
}
__global__ void colsum_hk(const __half* __restrict__ src, const float* __restrict__ wmask,
                          float* __restrict__ dst)
{
    const int b = blockIdx.x, c = blockIdx.y * 128 + threadIdx.x;
    const __half* S = src + (size_t)b * L_ * L_;
    float acc = 0.f;
#pragma unroll 4
    for (int r = 0; r < L_; r++) {
        float w = wmask ? wmask[b * L_ + r] : 1.f;
        acc = fmaf(__half2float(S[(size_t)r * L_ + c]), w, acc);
    }
    dst[b * L_ + c] = acc;
}
__global__ void qprop_k(const __half* __restrict__ cconvh)
{
    const int b = blockIdx.x, e = blockIdx.y * 128 + threadIdx.x;
    float acc = 0.f;
#pragma unroll 4
    for (int r = 0; r < L_; r++)
        acc = fmaf(g_colsumP[b * L_ + r],
                   __half2float(cconvh[((size_t)(b * L_ + r)) * E_ + e]), acc);
    g_q[b * E_ + e] = acc * g_msum[b];
}
__global__ void a12_k(const float* __restrict__ mask)
{
    const __half* eG = reinterpret_cast<const __half*>(g_G);
    __shared__ float s[32][33];
    const int b = blockIdx.z;
    const int i0 = blockIdx.y * 32, j0 = blockIdx.x * 32;
    const int tx = threadIdx.x, ty = threadIdx.y;
    const __half* Eb = eG + (size_t)b * L_ * L_;
    const float* mk = mask + b * L_;
    s[ty][tx] = __half2float(Eb[(size_t)(i0 + ty) * L_ + j0 + tx]);
    __syncthreads();
    float a1 = s[ty][tx] * mk[j0 + tx] / (g_rowsum[b * L_ + i0 + ty] + EPSF) * mk[i0 + ty];
    g_A1h[(size_t)b * L_ * L_ + (size_t)(i0 + ty) * L_ + j0 + tx] = __float2half_rn(a1);
    float a2 = s[tx][ty] * mk[i0 + tx] / (g_colsum[b * L_ + j0 + ty] + EPSF) * mk[j0 + ty];
    g_A2h[(size_t)b * L_ * L_ + (size_t)(j0 + ty) * L_ + i0 + tx] = __float2half_rn(a2);
}
__device__ __forceinline__ void red3(float& a0, float& a1, float& a2, int t)
{
#pragma unroll
    for (int o = 16; o > 0; o >>= 1) {
        a0 += __shfl_down_sync(0xffffffffu, a0, o);
        a1 += __shfl_down_sync(0xffffffffu, a1, o);
        a2 += __shfl_down_sync(0xffffffffu, a2, o);
    }
    __shared__ float sh[4][3];
    const int w = t >> 5, ln = t & 31;
    if (ln == 0) { sh[w][0] = a0; sh[w][1] = a1; sh[w][2] = a2; }
    __syncthreads();
    if (t == 0) {
        a0 = sh[0][0] + sh[1][0] + sh[2][0] + sh[3][0];
        a1 = sh[0][1] + sh[1][1] + sh[2][1] + sh[3][1];
        a2 = sh[0][2] + sh[1][2] + sh[2][2] + sh[3][2];
    }
}
__global__ void pk_k(const __half* __restrict__ Xh, int D,
                     const float* __restrict__ Wd, float* __restrict__ out)
{
    const int m = blockIdx.x, t = threadIdx.x;
    const __half2* xr = reinterpret_cast<const __half2*>(Xh + (size_t)m * D);
    float a0 = 0.f, a1 = 0.f, a2 = 0.f;
    for (int k2 = t; k2 < D / 2; k2 += 128) {
        float2 x = __half22float2(xr[k2]);
        const float* w = Wd + (size_t)(k2 * 2) * 3;
        a0 = fmaf(x.x, w[0], a0); a1 = fmaf(x.x, w[1], a1); a2 = fmaf(x.x, w[2], a2);
        a0 = fmaf(x.y, w[3], a0); a1 = fmaf(x.y, w[4], a1); a2 = fmaf(x.y, w[5], a2);
    }
    red3(a0, a1, a2, t);
    if (t == 0) {
        out[(size_t)m * 3 + 0] = a0;
        out[(size_t)m * 3 + 1] = a1;
        out[(size_t)m * 3 + 2] = a2;
    }
}
__global__ void xpred_k(const __half* __restrict__ Xh, const __half* __restrict__ Ah,
                        const float* __restrict__ Wd, const float* __restrict__ P,
                        const float* __restrict__ bd,
                        float* __restrict__ out, float* __restrict__ conf)
{
    const int m = blockIdx.x, t = threadIdx.x;
    const int b = m >> 9;
    float a0 = 0.f, a1 = 0.f, a2 = 0.f;
    const __half2* xr = reinterpret_cast<const __half2*>(Xh + (size_t)m * 512);
    for (int k2 = t; k2 < 256; k2 += 128) {
        float2 x = __half22float2(xr[k2]);
        const float* w = Wd + (size_t)(k2 * 2) * 3;
        a0 = fmaf(x.x, w[0], a0); a1 = fmaf(x.x, w[1], a1); a2 = fmaf(x.x, w[2], a2);
        a0 = fmaf(x.y, w[3], a0); a1 = fmaf(x.y, w[4], a1); a2 = fmaf(x.y, w[5], a2);
    }
    const __half2* ar = reinterpret_cast<const __half2*>(Ah + (size_t)m * 512);
    const float* Pb = P + (size_t)b * 512 * 3;
    for (int k2 = t; k2 < 256; k2 += 128) {
        float2 x = __half22float2(ar[k2]);
        const float* p = Pb + (size_t)(k2 * 2) * 3;
        a0 = fmaf(x.x, p[0], a0); a1 = fmaf(x.x, p[1], a1); a2 = fmaf(x.x, p[2], a2);
        a0 = fmaf(x.y, p[3], a0); a1 = fmaf(x.y, p[4], a1); a2 = fmaf(x.y, p[5], a2);
    }
    red3(a0, a1, a2, t);
    if (t == 0) {
        float p0 = a0 + bd[0], p1 = a1 + bd[1], p2 = a2 + bd[2];
        out[(size_t)m * 3 + 0] = p0;
        out[(size_t)m * 3 + 1] = p1;
        out[(size_t)m * 3 + 2] = p2;
        if (conf) {
            float mx = fmaxf(p0, fmaxf(p1, p2));
            float e0 = expf(p0 - mx), e1 = expf(p1 - mx), e2 = expf(p2 - mx);
            conf[m] = fmaxf(0.f, 1.f - 2.f * e0 / (e0 + e1 + e2));
        }
    }
}
__global__ void qs_k(const float* __restrict__ Wd)
{
    const int b = blockIdx.x, t = threadIdx.x;
    float a0 = 0.f, a1 = 0.f, a2 = 0.f;
    for (int k = t; k < 768; k += 128) {
        float x = g_q[b * 768 + k];
        const float* w = Wd + (size_t)k * 3;
        a0 = fmaf(x, w[0], a0); a1 = fmaf(x, w[1], a1); a2 = fmaf(x, w[2], a2);
    }
    red3(a0, a1, a2, t);
    if (t == 0) { g_qs[b * 3] = a0; g_qs[b * 3 + 1] = a1; g_qs[b * 3 + 2] = a2; }
}
__global__ void spred_k(const float* __restrict__ cq, const float* __restrict__ Wd,
                        const float* __restrict__ bd, float* __restrict__ out)
{
    const int m = blockIdx.x, t = threadIdx.x;
    const int b = m >> 9;
    float a0 = 0.f, a1 = 0.f, a2 = 0.f;
    const float* xr = cq + (size_t)m * 768;
    for (int k = t; k < 768; k += 128) {
        float x = xr[k];
        const float* w = Wd + (size_t)k * 3;
        a0 = fmaf(x, w[0], a0); a1 = fmaf(x, w[1], a1); a2 = fmaf(x, w[2], a2);
    }
    const __half2* ar = reinterpret_cast<const __half2*>(g_WAh + (size_t)m * 512);
    const float* Pb = g_Ps + (size_t)b * 512 * 3;
    for (int k2 = t; k2 < 256; k2 += 128) {
        float2 x = __half22float2(ar[k2]);
        const float* p = Pb + (size_t)(k2 * 2) * 3;
        a0 = fmaf(x.x, p[0], a0); a1 = fmaf(x.x, p[1], a1); a2 = fmaf(x.x, p[2], a2);
        a0 = fmaf(x.y, p[3], a0); a1 = fmaf(x.y, p[4], a1); a2 = fmaf(x.y, p[5], a2);
    }
    red3(a0, a1, a2, t);
    if (t == 0) {
        const float cf = g_conf[m];
        out[(size_t)m * 3 + 0] = a0 + bd[0] + cf * g_qs[b * 3 + 0];
        out[(size_t)m * 3 + 1] = a1 + bd[1] + cf * g_qs[b * 3 + 1];
        out[(size_t)m * 3 + 2] = a2 + bd[2] + cf * g_qs[b * 3 + 2];
    }
}
__global__ void msum_k(const float* __restrict__ mask)
{
    const int b = blockIdx.x, t = threadIdx.x;
    __shared__ float red[512];
    red[t] = mask[b * L_ + t]; __syncthreads();
    for (int st = 256; st > 0; st >>= 1) { if (t < st) red[t] += red[t + st]; __syncthreads(); }
    if (t == 0) g_msum[b] = red[0];
}
__global__ void smax_combine_k(const float* __restrict__ mask)
{
    const int row = blockIdx.x, t = threadIdx.x;
    const int b = row >> 9, i = row & 511;
    const size_t base = (size_t)row * L_;
    float v = g_WA[base + t];
    __shared__ float red[512];
    red[t] = v; __syncthreads();
    for (int st = 256; st > 0; st >>= 1) { if (t < st) red[t] = fmaxf(red[t], red[t + st]); __syncthreads(); }
    const float mx = red[0]; __syncthreads();
    float e = expf(v - mx) * mask[b * L_ + t];
    red[t] = e; __syncthreads();
    for (int st = 256; st > 0; st >>= 1) { if (t < st) red[t] += red[t + st]; __syncthreads(); }
    const float sum = red[0];
    float att = e / (sum + EPSF) * mask[b * L_ + i];
    g_WAh[base + t] = __float2half_rn(att + __half2float(g_A1h[base + t]));
}

// =====================================================================
extern "C" void kernel_launch(void* const* d_in, const int* in_sizes, int n_in,
                              void* d_out, int out_size)
{
    const float* aspect_in  = (const float*)d_in[0];
    const float* opinion_in = (const float*)d_in[1];
    const float* context_in = (const float*)d_in[2];
    const float* cq   = (const float*)d_in[3];
    const float* mask = (const float*)d_in[4];
    const float* pos  = (const float*)d_in[5];
    const float* Wa = (const float*)d_in[6],  *ba = (const float*)d_in[7];
    const float* Wo = (const float*)d_in[8],  *bo = (const float*)d_in[9];
    const float* Wc = (const float*)d_in[10], *bc = (const float*)d_in[11];
    const float* Wda = (const float*)d_in[12], *bda = (const float*)d_in[13];
    const float* Wdo = (const float*)d_in[14], *bdo = (const float*)d_in[15];
    const float* Wds = (const float*)d_in[16], *bds = (const float*)d_in[17];
    float* out = (float*)d_out;

    __half *ah, *oh, *ch, *cqh, *posh, *Wah, *Woh, *Wch;
    __half *aconvh, *oconvh, *cconvh, *cconvn, *T1h, *A1h, *A2h, *WAh;
    float *G, *WA, *inva, *invo, *invc, *colsum, *colsumP, *conf, *q;
    float *P1, *P1a, *Ps;
    cudaGetSymbolAddress((void**)&ah,     g_ah);
    cudaGetSymbolAddress((void**)&oh,     g_oh);
    cudaGetSymbolAddress((void**)&ch,     g_ch);
    cudaGetSymbolAddress((void**)&cqh,    g_cqh);
    cudaGetSymbolAddress((void**)&posh,   g_posh);
    cudaGetSymbolAddress((void**)&Wah,    g_Wah);
    cudaGetSymbolAddress((void**)&Woh,    g_Woh);
    cudaGetSymbolAddress((void**)&Wch,    g_Wch);
    cudaGetSymbolAddress((void**)&aconvh, g_aconvh);
    cudaGetSymbolAddress((void**)&oconvh, g_oconvh);
    cudaGetSymbolAddress((void**)&cconvh, g_cconvh);
    cudaGetSymbolAddress((void**)&cconvn, g_cconvn);
    cudaGetSymbolAddress((void**)&T1h,    g_T1h);
    cudaGetSymbolAddress((void**)&A1h,    g_A1h);
    cudaGetSymbolAddress((void**)&A2h,    g_A2h);
    cudaGetSymbolAddress((void**)&WAh,    g_WAh);
    cudaGetSymbolAddress((void**)&G,      g_G);
    cudaGetSymbolAddress((void**)&WA,     g_WA);
    cudaGetSymbolAddress((void**)&inva,   g_inva);
    cudaGetSymbolAddress((void**)&invo,   g_invo);
    cudaGetSymbolAddress((void**)&invc,   g_invc);
    cudaGetSymbolAddress((void**)&colsum, g_colsum);
    cudaGetSymbolAddress((void**)&colsumP,g_colsumP);
    cudaGetSymbolAddress((void**)&conf,   g_conf);
    cudaGetSymbolAddress((void**)&q,      g_q);
    cudaGetSymbolAddress((void**)&P1,     g_P1);
    cudaGetSymbolAddress((void**)&P1a,    g_P1a);
    cudaGetSymbolAddress((void**)&Ps,     g_Ps);
    __half* eGh = reinterpret_cast<__half*>(G);

    cudaFuncSetAttribute(tc_gemm<true, true, false>,   cudaFuncAttributeMaxDynamicSharedMemorySize, SMEM_DYN);
    cudaFuncSetAttribute(tc_gemm<false, true, false>,  cudaFuncAttributeMaxDynamicSharedMemorySize, SMEM_DYN);
    cudaFuncSetAttribute(tc_gemm<false, false, false>, cudaFuncAttributeMaxDynamicSharedMemorySize, SMEM_DYN);
    cudaFuncSetAttribute(tc_gemm<false, true, true>,   cudaFuncAttributeMaxDynamicSharedMemorySize, SMEM_DYN);

    static cudaStream_t s1 = nullptr, s2 = nullptr;
    static cudaEvent_t ev[12] = {};
    if (!s1) {
        cudaStreamCreateWithFlags(&s1, cudaStreamNonBlocking);
        cudaStreamCreateWithFlags(&s2, cudaStreamNonBlocking);
        for (int i = 0; i < 12; i++) cudaEventCreateWithFlags(&ev[i], cudaEventDisableTiming);
    }
    cudaEvent_t evRoot = ev[0], evPos = ev[1], ev1 = ev[2], ev2 = ev[3],
                evA12 = ev[4], evConf = ev[5], evE1 = ev[6], evC2 = ev[7],
                evP1a = ev[8], evSmax = ev[9];

    // ---- FORK ----
    cudaEventRecord(evRoot, 0);
    cudaStreamWaitEvent(s1, evRoot, 0);
    cudaStreamWaitEvent(s2, evRoot, 0);

    const int nIN = M_ * E_ / 4, nPOS = B_ * L_ * L_ / 4;

    // default: aspect path
    cvt_k<<<(nIN + 255) / 256, 256>>>((const float4*)aspect_in, (uint2*)ah, nIN);
    cvt_k<<<(2304 * 512 / 4 + 255) / 256, 256>>>((const float4*)Wa, (uint2*)Wah, 2304 * 512 / 4);
    tc_gemm<true, true, false><<<dim3(128, 4, 1), 256, SMEM_DYN>>>(
        ah, 0, 2304, Wah, 0, 512, 2304, out + OFF_AINT, 0, 1024, ba,
        nullptr, nullptr, nullptr, nullptr, nullptr, nullptr, 0, aconvh, 0, 512, 0);
    rowinv_h<<<M_, 256>>>(aconvh, 512, inva);

    // s1: opinion path, P1a, then pos/cq conversions
    cvt_k<<<(2304 * 512 / 4 + 255) / 256, 256, 0, s1>>>((const float4*)Wo, (uint2*)Woh, 2304 * 512 / 4);
    cvt_k<<<(nIN + 255) / 256, 256, 0, s1>>>((const float4*)opinion_in, (uint2*)oh, nIN);
    tc_gemm<true, true, false><<<dim3(128, 4, 1), 256, SMEM_DYN, s1>>>(
        oh, 0, 2304, Woh, 0, 512, 2304, out + OFF_OINT, 0, 1024, bo,
        nullptr, nullptr, nullptr, nullptr, nullptr, nullptr, 0, oconvh, 0, 512, 0);
    rowinv_h<<<M_, 256, 0, s1>>>(oconvh, 512, invo);
    cudaEventRecord(ev1, s1);
    pk_k<<<M_, 128, 0, s1>>>(oconvh, 512, Wda + 512 * 3, P1a);
    cudaEventRecord(evP1a, s1);
    cvt_k<<<(nPOS + 255) / 256, 256, 0, s1>>>((const float4*)pos, (uint2*)posh, nPOS);
    cvt_k<<<(nIN + 255) / 256, 256, 0, s1>>>((const float4*)cq, (uint2*)cqh, nIN);
    cudaEventRecord(evPos, s1);

    // s2: context path + Ps
    cvt_k<<<(2304 * 768 / 4 + 255) / 256, 256, 0, s2>>>((const float4*)Wc, (uint2*)Wch, 2304 * 768 / 4);
    cvt_k<<<(nIN + 255) / 256, 256, 0, s2>>>((const float4*)context_in, (uint2*)ch, nIN);
    tc_gemm<true, true, false><<<dim3(128, 6, 1), 256, SMEM_DYN, s2>>>(
        ch, 0, 2304, Wch, 0, 768, 2304, out + OFF_CCONV, 0, 768, bc,
        nullptr, nullptr, nullptr, nullptr, nullptr, nullptr, 0, cconvh, 0, 768, 0);
    rowinv_h<<<M_, 256, 0, s2>>>(cconvh, 768, invc);
    scalec_k<<<(M_ * 384 + 255) / 256, 256, 0, s2>>>();
    cudaEventRecord(ev2, s2);
    pk_k<<<M_, 128, 0, s2>>>(cconvh, 768, Wds, Ps);

    // ---- chain A (default): gram -> fp16 expG -> softmasks -> apred -> A1 GEMM
    cudaStreamWaitEvent(0, ev1, 0);
    tc_gemm<false, false, false><<<dim3(4, 4, B_), 256, SMEM_DYN>>>(
        aconvh, 512LL * 512, 512, oconvh, 512LL * 512, 512, 512, nullptr, 0, 512,
        nullptr, inva, invo, nullptr, nullptr, nullptr, nullptr, 0, eGh, 512LL * 512, 512, 1);
    rowsum_k<<<M_, 512>>>(mask);
    colsum_hk<<<dim3(B_, 4), 128>>>(eGh, mask, colsum);
    a12_k<<<dim3(16, 16, B_), dim3(32, 32)>>>(mask);
    cudaEventRecord(evA12, 0);
    cudaStreamWaitEvent(0, evP1a, 0);
    xpred_k<<<M_, 128>>>(aconvh, A1h, Wda, P1a, bda, out + OFF_APRED, nullptr);
    tc_gemm<false, true, false><<<dim3(4, 4, B_), 256, SMEM_DYN>>>(
        A1h, 512LL * 512, 512, oconvh, 512LL * 512, 512, 512, out + OFF_AINT + 512, 512LL * 1024, 1024,
        nullptr, nullptr, nullptr, nullptr, nullptr, nullptr, nullptr, 0, nullptr, 0, 0, 0);

    // ---- chain B (s1): reassociated context attention
    //  T1t[k,e] = sum_j pos[j,k] * cconvn[j,e]   (TN: A=posh [j,k], B=cconvn [j,e])
    cudaStreamWaitEvent(s1, ev2, 0);
    tc_gemm<false, true, true><<<dim3(4, 6, B_), 256, SMEM_DYN, s1>>>(
        posh, 512LL * 512, 512, cconvn, 512LL * 768, 768, 512, nullptr, 0, 768,
        nullptr, nullptr, nullptr, nullptr, nullptr, nullptr, nullptr, 0, T1h, 512LL * 768, 768, 0);
    //  WA[i,k] = sum_e cq[i,e] * T1t[k,e]        (NT)
    tc_gemm<false, false, false><<<dim3(4, 4, B_), 256, SMEM_DYN, s1>>>(
        cqh, 512LL * 768, 768, T1h, 512LL * 768, 768, 768, WA, 512LL * 512, 512,
        nullptr, nullptr, nullptr, nullptr, nullptr, nullptr, nullptr, 0, nullptr, 0, 0, 0);
    cudaStreamWaitEvent(s1, evA12, 0);
    smax_combine_k<<<M_, 512, 0, s1>>>(mask);
    cudaEventRecord(evSmax, s1);

    // ---- chain C (s2): propagation pieces, fast conf, spred, A2 GEMM
    cudaStreamWaitEvent(s2, evPos, 0);
    colsum_hk<<<dim3(B_, 4), 128, 0, s2>>>(posh, nullptr, colsumP);
    msum_k<<<B_, 512, 0, s2>>>(mask);
    qprop_k<<<dim3(B_, 6), 128, 0, s2>>>(cconvh);
    qs_k<<<B_, 128, 0, s2>>>(Wds);
    cudaStreamWaitEvent(s2, evA12, 0);
    pk_k<<<M_, 128, 0, s2>>>(aconvh, 512, Wdo + 512 * 3, P1);
    xpred_k<<<M_, 128, 0, s2>>>(oconvh, A2h, Wdo, P1, bdo, out + OFF_OPRED, conf);
    cudaEventRecord(evConf, s2);
    cudaStreamWaitEvent(s2, evSmax, 0);
    spred_k<<<M_, 128, 0, s2>>>(cq, Wds, bds, out + OFF_SPRED);
    tc_gemm<false, true, false><<<dim3(4, 4, B_), 256, SMEM_DYN, s2>>>(
        A2h, 512LL * 512, 512, aconvh, 512LL * 512, 512, 512, out + OFF_OINT + 512, 512LL * 1024, 1024,
        nullptr, nullptr, nullptr, nullptr, nullptr, nullptr, nullptr, 0, nullptr, 0, 0, 0);
    cudaEventRecord(evC2, s2);

    // ---- s1 tail: final context GEMM
    cudaStreamWaitEvent(s1, evConf, 0);
    tc_gemm<false, true, false><<<dim3(4, 6, B_), 256, SMEM_DYN, s1>>>(
        WAh, 512LL * 512, 512, cconvh, 512LL * 768, 768, 512, out + OFF_CINT, 512LL * 768, 768,
        nullptr, nullptr, nullptr, cq, conf, q, nullptr, 0, nullptr, 0, 0, 0);
    cudaEventRecord(evE1, s1);

    // ---- join ----
    cudaStreamWaitEvent(0, evE1, 0);
    cudaStreamWaitEvent(0, evC2, 0);
}

// round 16
// speedup vs baseline: 1.0051x; 1.0051x over previous
#include <cuda_runtime.h>
#include <cuda_fp16.h>
#include <cstdint>
#include <cstddef>

#define B_  32
#define L_  512
#define E_  768
#define F_  512
#define M_  (B_ * L_)
#define EPSF 1e-7f

#define OFF_APRED 0L
#define OFF_OPRED 49152L
#define OFF_SPRED 98304L
#define OFF_AINT  147456L
#define OFF_OINT  16924672L
#define OFF_CINT  33701888L
#define OFF_CCONV 46284800L

__device__ __half g_ah  [(size_t)M_ * E_];
__device__ __half g_oh  [(size_t)M_ * E_];
__device__ __half g_ch  [(size_t)M_ * E_];
__device__ __half g_cqh [(size_t)M_ * E_];
__device__ __half g_posh[(size_t)B_ * L_ * L_];
__device__ __half g_Wah [2304 * 512];
__device__ __half g_Woh [2304 * 512];
__device__ __half g_Wch [2304 * 768];
__device__ __half g_aconvh[(size_t)M_ * F_];
__device__ __half g_oconvh[(size_t)M_ * F_];
__device__ __half g_cconvh[(size_t)M_ * E_];
__device__ __half g_A1h[(size_t)B_ * L_ * L_];
__device__ __half g_A2h[(size_t)B_ * L_ * L_];
__device__ __half g_Gh [(size_t)B_ * L_ * L_];
__device__ __half g_WAh[(size_t)B_ * L_ * L_];
__device__ float g_G [(size_t)B_ * L_ * L_];   // first half reused as fp16 expG
__device__ float g_WA[(size_t)B_ * L_ * L_];
__device__ float g_inva[M_], g_invo[M_], g_invc[M_];
__device__ float g_colsumP[M_];
__device__ float g_rowpart[(size_t)M_ * 4];
__device__ float g_colpart[(size_t)M_ * 4];
__device__ float g_msum[B_];
__device__ float g_conf[M_];
__device__ float g_q[(size_t)B_ * E_];
__device__ float g_P1 [(size_t)M_ * 3];
__device__ float g_P1a[(size_t)M_ * 3];
__device__ float g_Ps [(size_t)M_ * 3];
__device__ float g_qs [B_ * 3];

// ---------------- helpers ----------------
__device__ __forceinline__ uint32_t su32(const void* p) {
    uint32_t a;
    asm("{ .reg .u64 t; cvta.to.shared.u64 t, %1; cvt.u32.u64 %0, t; }" : "=r"(a) : "l"(p));
    return a;
}
__device__ __forceinline__ void ldm_x4(uint32_t* r, uint32_t addr) {
    asm volatile("ldmatrix.sync.aligned.m8n8.x4.shared.b16 {%0,%1,%2,%3}, [%4];"
                 : "=r"(r[0]), "=r"(r[1]), "=r"(r[2]), "=r"(r[3]) : "r"(addr));
}
__device__ __forceinline__ void ldm_x4t(uint32_t* r, uint32_t addr) {
    asm volatile("ldmatrix.sync.aligned.m8n8.x4.trans.shared.b16 {%0,%1,%2,%3}, [%4];"
                 : "=r"(r[0]), "=r"(r[1]), "=r"(r[2]), "=r"(r[3]) : "r"(addr));
}
__device__ __forceinline__ void mma_f16(float* c, const uint32_t* a, const uint32_t* b) {
    asm volatile(
        "mma.sync.aligned.m16n8k16.row.col.f32.f16.f16.f32 "
        "{%0,%1,%2,%3}, {%4,%5,%6,%7}, {%8,%9}, {%0,%1,%2,%3};"
        : "+f"(c[0]), "+f"(c[1]), "+f"(c[2]), "+f"(c[3])
        : "r"(a[0]), "r"(a[1]), "r"(a[2]), "r"(a[3]), "r"(b[0]), "r"(b[1]));
}
__device__ __forceinline__ uint32_t pkh(float x, float y) {
    __half2 t = __floats2half2_rn(x, y);
    return *reinterpret_cast<uint32_t*>(&t);
}

// ---------------- fp16 tensor-core GEMM, BK=64, one barrier/chunk ----------------
#define AROWB 144
#define NROWB 272
#define S_B   18432
#define STAGE 36864
#define SMEM_DYN (2 * STAGE)

template<bool GATHER, bool BNN>
__global__ __launch_bounds__(256, 2)
void tc_gemm(const __half* __restrict__ A, long long ab,
             const __half* __restrict__ Bm, long long bb, int ldb, int K,
             float* __restrict__ C, long long cb, int ldc,
             const float* __restrict__ bias,
             const float* __restrict__ rs, const float* __restrict__ cs,
             const float* __restrict__ addp,
             const float* __restrict__ rowv, const float* __restrict__ colv,
             float* __restrict__ C2, int ldc2,
             __half* __restrict__ Ch, long long cbh, int ldch,
             int doexp,
             const float* __restrict__ smask,
             float* __restrict__ rowpart, float* __restrict__ colpart)
{
    extern __shared__ char smem[];
    const int tid = threadIdx.x;
    const int lane = tid & 31, wid = tid >> 5;
    const int wm = wid & 3, wn = wid >> 2;
    const int m0 = blockIdx.x * 128, n0 = blockIdx.y * 128, bz = blockIdx.z;
    const uint32_t sb0 = su32(smem);

    const __half* Ab = GATHER ? A : (A + (size_t)bz * ab);
    const __half* Bb = Bm + (size_t)bz * bb;

    float c[2][8][4];
#pragma unroll
    for (int i = 0; i < 2; i++)
#pragma unroll
        for (int j = 0; j < 8; j++)
#pragma unroll
            for (int k = 0; k < 4; k++) c[i][j][k] = 0.f;

    const int nch = K / 64;
    uint4 va[4], vb[4];

    auto ldg = [&](int kc) {
        const int k0 = kc * 64;
#pragma unroll
        for (int p = 0; p < 4; p++) {
            const int idx = tid + p * 256, row = idx >> 3, c16 = idx & 7;
            if (GATHER) {
                const int gm = m0 + row, b = gm >> 9, l = gm & 511;
                const int tap = kc / 12, e0 = (kc - tap * 12) * 64;
                const int src = l + tap - 1;
                va[p] = ((unsigned)src < 512u)
                    ? *reinterpret_cast<const uint4*>(A + ((size_t)(b * 512 + src)) * 768 + e0 + c16 * 8)
                    : make_uint4(0u, 0u, 0u, 0u);
            } else {
                va[p] = *reinterpret_cast<const uint4*>(Ab + (size_t)(m0 + row) * K + k0 + c16 * 8);
            }
        }
        if (BNN) {
#pragma unroll
            for (int p = 0; p < 4; p++) {
                const int idx = tid + p * 256, kr = idx >> 4, c16 = idx & 15;
                vb[p] = *reinterpret_cast<const uint4*>(Bb + (size_t)(k0 + kr) * ldb + n0 + c16 * 8);
            }
        } else {
#pragma unroll
            for (int p = 0; p < 4; p++) {
                const int idx = tid + p * 256, row = idx >> 3, c16 = idx & 7;
                vb[p] = *reinterpret_cast<const uint4*>(Bb + (size_t)(n0 + row) * ldb + k0 + c16 * 8);
            }
        }
    };
    auto sts = [&](int s) {
        char* sp = smem + s * STAGE;
#pragma unroll
        for (int p = 0; p < 4; p++) {
            const int idx = tid + p * 256, row = idx >> 3, c16 = idx & 7;
            *reinterpret_cast<uint4*>(sp + row * AROWB + c16 * 16) = va[p];
        }
        if (BNN) {
#pragma unroll
            for (int p = 0; p < 4; p++) {
                const int idx = tid + p * 256, kr = idx >> 4, c16 = idx & 15;
                *reinterpret_cast<uint4*>(sp + S_B + kr * NROWB + c16 * 16) = vb[p];
            }
        } else {
#pragma unroll
            for (int p = 0; p < 4; p++) {
                const int idx = tid + p * 256, row = idx >> 3, c16 = idx & 7;
                *reinterpret_cast<uint4*>(sp + S_B + row * AROWB + c16 * 16) = vb[p];
            }
        }
    };

    const uint32_t a_lrow = (lane & 15), a_lcol = (lane >> 4) * 8;
    const uint32_t nt_lrow = (lane & 7) + ((lane >> 4) << 3), nt_lcol = ((lane >> 3) & 1) * 8;
    const uint32_t nn_krow = (lane & 7) + (((lane >> 3) & 1) << 3), nn_ncol = (lane >> 4) * 8;

    auto compute = [&](int s) {
        const uint32_t base = sb0 + s * STAGE;
#pragma unroll
        for (int ks = 0; ks < 4; ks++) {
            const int kk = ks * 16;
            uint32_t af[2][4];
#pragma unroll
            for (int mf = 0; mf < 2; mf++)
                ldm_x4(af[mf], base + (wm * 32 + mf * 16 + a_lrow) * AROWB + (kk + a_lcol) * 2);
#pragma unroll
            for (int nf2 = 0; nf2 < 4; nf2++) {
                uint32_t bt[4];
                if (BNN)
                    ldm_x4t(bt, base + S_B + (kk + nn_krow) * NROWB + (wn * 64 + nf2 * 16 + nn_ncol) * 2);
                else
                    ldm_x4(bt, base + S_B + (wn * 64 + nf2 * 16 + nt_lrow) * AROWB + (kk + nt_lcol) * 2);
#pragma unroll
                for (int mf = 0; mf < 2; mf++) {
                    mma_f16(c[mf][nf2 * 2 + 0], af[mf], bt);
                    mma_f16(c[mf][nf2 * 2 + 1], af[mf], bt + 2);
                }
            }
        }
    };

    ldg(0);
    sts(0);
    ldg(1);
    __syncthreads();
    for (int i = 0; i < nch; i++) {
        if (i + 1 < nch) sts((i + 1) & 1);
        if (i + 2 < nch) ldg(i + 2);
        compute(i & 1);
        __syncthreads();
    }

    const int tm = lane >> 2, tn = (lane & 3) * 2;
    float racc[2][2] = {{0.f, 0.f}, {0.f, 0.f}};
    float cacc[8][2];
#pragma unroll
    for (int j = 0; j < 8; j++) { cacc[j][0] = 0.f; cacc[j][1] = 0.f; }

#pragma unroll
    for (int mf = 0; mf < 2; mf++) {
#pragma unroll
        for (int nf = 0; nf < 8; nf++) {
#pragma unroll
            for (int half = 0; half < 2; half++) {
                const int m = m0 + wm * 32 + mf * 16 + tm + half * 8;
                const int nn = n0 + wn * 64 + nf * 8 + tn;
                float v0 = c[mf][nf][half * 2 + 0];
                float v1 = c[mf][nf][half * 2 + 1];
                if (rs) { const float r = rs[bz * 512 + m]; v0 *= r; v1 *= r; }
                if (cs) { v0 *= cs[bz * 512 + nn]; v1 *= cs[bz * 512 + nn + 1]; }
                if (doexp) { v0 = expf(v0); v1 = expf(v1); }
                if (bias) {
                    v0 = fmaxf(v0 + bias[nn], 0.f);
                    v1 = fmaxf(v1 + bias[nn + 1], 0.f);
                }
                if (C) {
                    const size_t rowoff = (size_t)bz * cb + (size_t)m * ldc + nn;
                    if (addp) { v0 += addp[rowoff]; v1 += addp[rowoff + 1]; }
                    if (rowv) {
                        const float rv = rowv[bz * 512 + m];
                        v0 += rv * colv[(size_t)bz * ldc + nn];
                        v1 += rv * colv[(size_t)bz * ldc + nn + 1];
                    }
                    C[rowoff] = v0; C[rowoff + 1] = v1;
                }
                if (C2) {
                    float* c2 = C2 + (size_t)m * ldc2 + nn;
                    c2[0] = v0; c2[1] = v1;
                }
                if (Ch) {
                    *reinterpret_cast<__half2*>(Ch + (size_t)bz * cbh + (size_t)m * ldch + nn) =
                        __floats2half2_rn(v0, v1);
                }
                if (rowpart) {
                    const float mc0 = smask[bz * 512 + nn], mc1 = smask[bz * 512 + nn + 1];
                    const float mrow = smask[bz * 512 + m];
                    racc[mf][half] += v0 * mc0 + v1 * mc1;
                    cacc[nf][0] += v0 * mrow;
                    cacc[nf][1] += v1 * mrow;
                }
            }
        }
    }

    // ---- fused masked row/col partial sums (gram only) ----
    if (rowpart) {
        float* rowred = reinterpret_cast<float*>(smem);        // 256 floats
        float* colred = rowred + 256;                          // 512 floats
#pragma unroll
        for (int mf = 0; mf < 2; mf++)
#pragma unroll
            for (int half = 0; half < 2; half++) {
                float r = racc[mf][half];
                r += __shfl_down_sync(0xffffffffu, r, 2, 4);
                r += __shfl_down_sync(0xffffffffu, r, 1, 4);
                if ((lane & 3) == 0)
                    rowred[(((wn * 4 + wm) * 2 + mf) * 2 + half) * 8 + tm] = r;
            }
#pragma unroll
        for (int nf = 0; nf < 8; nf++)
#pragma unroll
            for (int j = 0; j < 2; j++) {
                float cv = cacc[nf][j];
                cv += __shfl_down_sync(0xffffffffu, cv, 16);
                cv += __shfl_down_sync(0xffffffffu, cv, 8);
                cv += __shfl_down_sync(0xffffffffu, cv, 4);
                if (lane < 4)
                    colred[(((wm * 2 + wn) * 8 + nf) * 2 + j) * 4 + lane] = cv;
            }
        __syncthreads();
        if (tid < 128) {
            const int tm_ = tid & 7, half_ = (tid >> 3) & 1, mf_ = (tid >> 4) & 1, wm_ = (tid >> 5) & 3;
            const float s = rowred[(((0 * 4 + wm_) * 2 + mf_) * 2 + half_) * 8 + tm_] +
                            rowred[(((1 * 4 + wm_) * 2 + mf_) * 2 + half_) * 8 + tm_];
            const int m = m0 + wm_ * 32 + mf_ * 16 + tm_ + half_ * 8;
            rowpart[((size_t)bz * 512 + m) * 4 + blockIdx.y] = s;
        } else {
            const int idx = tid - 128;
            const int l4 = idx & 3, j_ = (idx >> 2) & 1, nf_ = (idx >> 3) & 7, wn_ = (idx >> 6) & 1;
            float s = 0.f;
#pragma unroll
            for (int wm_ = 0; wm_ < 4; wm_++)
                s += colred[(((wm_ * 2 + wn_) * 8 + nf_) * 2 + j_) * 4 + l4];
            const int col = n0 + wn_ * 64 + nf_ * 8 + l4 * 2 + j_;
            colpart[((size_t)bz * 512 + col) * 4 + blockIdx.x] = s;
        }
    }
}

// ---------------- small kernels ----------------
__global__ void cvt_k(const float4* __restrict__ src, uint2* __restrict__ dst, int n4)
{
    const int i = blockIdx.x * 256 + threadIdx.x;
    if (i < n4) {
        float4 v = src[i];
        dst[i] = make_uint2(pkh(v.x, v.y), pkh(v.z, v.w));
    }
}
__global__ void rowinv_h(const __half* __restrict__ X, int D, float* __restrict__ inv)
{
    const int m = blockIdx.x, t = threadIdx.x;
    float s = 0.f;
    const __half2* xr = reinterpret_cast<const __half2*>(X + (size_t)m * D);
    for (int k = t; k < D / 2; k += 256) {
        float2 v = __half22float2(xr[k]);
        s = fmaf(v.x, v.x, fmaf(v.y, v.y, s));
    }
    __shared__ float red[256];
    red[t] = s; __syncthreads();
    for (int st = 128; st > 0; st >>= 1) { if (t < st) red[t] += red[t + st]; __syncthreads(); }
    if (t == 0) inv[m] = rsqrtf(fmaxf(red[0], 1e-12f));
}
__global__ void colsum_hk(const __half* __restrict__ src, float* __restrict__ dst)
{
    const int b = blockIdx.x, c = blockIdx.y * 128 + threadIdx.x;
    const __half* S = src + (size_t)b * L_ * L_;
    float acc = 0.f;
#pragma unroll 4
    for (int r = 0; r < L_; r++)
        acc += __half2float(S[(size_t)r * L_ + c]);
    dst[b * L_ + c] = acc;
}
__global__ void qprop_k(const __half* __restrict__ cconvh)
{
    const int b = blockIdx.x, e = blockIdx.y * 128 + threadIdx.x;
    float acc = 0.f;
#pragma unroll 4
    for (int r = 0; r < L_; r++)
        acc = fmaf(g_colsumP[b * L_ + r],
                   __half2float(cconvh[((size_t)(b * L_ + r)) * E_ + e]), acc);
    g_q[b * E_ + e] = acc * g_msum[b];
}
__global__ void a12_k(const float* __restrict__ mask)
{
    const __half* eG = reinterpret_cast<const __half*>(g_G);
    __shared__ float s[32][33];
    __shared__ float rsum[32], csum[32];
    const int b = blockIdx.z;
    const int i0 = blockIdx.y * 32, j0 = blockIdx.x * 32;
    const int tx = threadIdx.x, ty = threadIdx.y;
    const __half* Eb = eG + (size_t)b * L_ * L_;
    const float* mk = mask + b * L_;
    s[ty][tx] = __half2float(Eb[(size_t)(i0 + ty) * L_ + j0 + tx]);
    if (tx == 0) {
        float v = 0.f;
#pragma unroll
        for (int k = 0; k < 4; k++) v += g_rowpart[((size_t)(b * 512) + i0 + ty) * 4 + k];
        rsum[ty] = v;
    }
    if (tx == 1) {
        float v = 0.f;
#pragma unroll
        for (int k = 0; k < 4; k++) v += g_colpart[((size_t)(b * 512) + j0 + ty) * 4 + k];
        csum[ty] = v;
    }
    __syncthreads();
    float a1 = s[ty][tx] * mk[j0 + tx] / (rsum[ty] + EPSF) * mk[i0 + ty];
    g_A1h[(size_t)b * L_ * L_ + (size_t)(i0 + ty) * L_ + j0 + tx] = __float2half_rn(a1);
    float a2 = s[tx][ty] * mk[i0 + tx] / (csum[ty] + EPSF) * mk[j0 + ty];
    g_A2h[(size_t)b * L_ * L_ + (size_t)(j0 + ty) * L_ + i0 + tx] = __float2half_rn(a2);
}
__device__ __forceinline__ void red3(float& a0, float& a1, float& a2, int t)
{
#pragma unroll
    for (int o = 16; o > 0; o >>= 1) {
        a0 += __shfl_down_sync(0xffffffffu, a0, o);
        a1 += __shfl_down_sync(0xffffffffu, a1, o);
        a2 += __shfl_down_sync(0xffffffffu, a2, o);
    }
    __shared__ float sh[4][3];
    const int w = t >> 5, ln = t & 31;
    if (ln == 0) { sh[w][0] = a0; sh[w][1] = a1; sh[w][2] = a2; }
    __syncthreads();
    if (t == 0) {
        a0 = sh[0][0] + sh[1][0] + sh[2][0] + sh[3][0];
        a1 = sh[0][1] + sh[1][1] + sh[2][1] + sh[3][1];
        a2 = sh[0][2] + sh[1][2] + sh[2][2] + sh[3][2];
    }
}
__global__ void pk_k(const __half* __restrict__ Xh, int D,
                     const float* __restrict__ Wd, float* __restrict__ out)
{
    const int m = blockIdx.x, t = threadIdx.x;
    const __half2* xr = reinterpret_cast<const __half2*>(Xh + (size_t)m * D);
    float a0 = 0.f, a1 = 0.f, a2 = 0.f;
    for (int k2 = t; k2 < D / 2; k2 += 128) {
        float2 x = __half22float2(xr[k2]);
        const float* w = Wd + (size_t)(k2 * 2) * 3;
        a0 = fmaf(x.x, w[0], a0); a1 = fmaf(x.x, w[1], a1); a2 = fmaf(x.x, w[2], a2);
        a0 = fmaf(x.y, w[3], a0); a1 = fmaf(x.y, w[4], a1); a2 = fmaf(x.y, w[5], a2);
    }
    red3(a0, a1, a2, t);
    if (t == 0) {
        out[(size_t)m * 3 + 0] = a0;
        out[(size_t)m * 3 + 1] = a1;
        out[(size_t)m * 3 + 2] = a2;
    }
}
__global__ void xpred_k(const __half* __restrict__ Xh, const __half* __restrict__ Ah,
                        const float* __restrict__ Wd, const float* __restrict__ P,
                        const float* __restrict__ bd,
                        float* __restrict__ out, float* __restrict__ conf)
{
    const int m = blockIdx.x, t = threadIdx.x;
    const int b = m >> 9;
    float a0 = 0.f, a1 = 0.f, a2 = 0.f;
    const __half2* xr = reinterpret_cast<const __half2*>(Xh + (size_t)m * 512);
    for (int k2 = t; k2 < 256; k2 += 128) {
        float2 x = __half22float2(xr[k2]);
        const float* w = Wd + (size_t)(k2 * 2) * 3;
        a0 = fmaf(x.x, w[0], a0); a1 = fmaf(x.x, w[1], a1); a2 = fmaf(x.x, w[2], a2);
        a0 = fmaf(x.y, w[3], a0); a1 = fmaf(x.y, w[4], a1); a2 = fmaf(x.y, w[5], a2);
    }
    const __half2* ar = reinterpret_cast<const __half2*>(Ah + (size_t)m * 512);
    const float* Pb = P + (size_t)b * 512 * 3;
    for (int k2 = t; k2 < 256; k2 += 128) {
        float2 x = __half22float2(ar[k2]);
        const float* p = Pb + (size_t)(k2 * 2) * 3;
        a0 = fmaf(x.x, p[0], a0); a1 = fmaf(x.x, p[1], a1); a2 = fmaf(x.x, p[2], a2);
        a0 = fmaf(x.y, p[3], a0); a1 = fmaf(x.y, p[4], a1); a2 = fmaf(x.y, p[5], a2);
    }
    red3(a0, a1, a2, t);
    if (t == 0) {
        float p0 = a0 + bd[0], p1 = a1 + bd[1], p2 = a2 + bd[2];
        out[(size_t)m * 3 + 0] = p0;
        out[(size_t)m * 3 + 1] = p1;
        out[(size_t)m * 3 + 2] = p2;
        if (conf) {
            float mx = fmaxf(p0, fmaxf(p1, p2));
            float e0 = expf(p0 - mx), e1 = expf(p1 - mx), e2 = expf(p2 - mx);
            conf[m] = fmaxf(0.f, 1.f - 2.f * e0 / (e0 + e1 + e2));
        }
    }
}
__global__ void qs_k(const float* __restrict__ Wd)
{
    const int b = blockIdx.x, t = threadIdx.x;
    float a0 = 0.f, a1 = 0.f, a2 = 0.f;
    for (int k = t; k < 768; k += 128) {
        float x = g_q[b * 768 + k];
        const float* w = Wd + (size_t)k * 3;
        a0 = fmaf(x, w[0], a0); a1 = fmaf(x, w[1], a1); a2 = fmaf(x, w[2], a2);
    }
    red3(a0, a1, a2, t);
    if (t == 0) { g_qs[b * 3] = a0; g_qs[b * 3 + 1] = a1; g_qs[b * 3 + 2] = a2; }
}
__global__ void spred_k(const float* __restrict__ cq, const float* __restrict__ Wd,
                        const float* __restrict__ bd, float* __restrict__ out)
{
    const int m = blockIdx.x, t = threadIdx.x;
    const int b = m >> 9;
    float a0 = 0.f, a1 = 0.f, a2 = 0.f;
    const float* xr = cq + (size_t)m * 768;
    for (int k = t; k < 768; k += 128) {
        float x = xr[k];
        const float* w = Wd + (size_t)k * 3;
        a0 = fmaf(x, w[0], a0); a1 = fmaf(x, w[1], a1); a2 = fmaf(x, w[2], a2);
    }
    const __half2* ar = reinterpret_cast<const __half2*>(g_WAh + (size_t)m * 512);
    const float* Pb = g_Ps + (size_t)b * 512 * 3;
    for (int k2 = t; k2 < 256; k2 += 128) {
        float2 x = __half22float2(ar[k2]);
        const float* p = Pb + (size_t)(k2 * 2) * 3;
        a0 = fmaf(x.x, p[0], a0); a1 = fmaf(x.x, p[1], a1); a2 = fmaf(x.x, p[2], a2);
        a0 = fmaf(x.y, p[3], a0); a1 = fmaf(x.y, p[4], a1); a2 = fmaf(x.y, p[5], a2);
    }
    red3(a0, a1, a2, t);
    if (t == 0) {
        const float cf = g_conf[m];
        out[(size_t)m * 3 + 0] = a0 + bd[0] + cf * g_qs[b * 3 + 0];
        out[(size_t)m * 3 + 1] = a1 + bd[1] + cf * g_qs[b * 3 + 1];
        out[(size_t)m * 3 + 2] = a2 + bd[2] + cf * g_qs[b * 3 + 2];
    }
}
__global__ void msum_k(const float* __restrict__ mask)
{
    const int b = blockIdx.x, t = threadIdx.x;
    __shared__ float red[512];
    red[t] = mask[b * L_ + t]; __syncthreads();
    for (int st = 256; st > 0; st >>= 1) { if (t < st) red[t] += red[t + st]; __syncthreads(); }
    if (t == 0) g_msum[b] = red[0];
}
__global__ void smax_combine_k(const float* __restrict__ mask)
{
    const int row = blockIdx.x, t = threadIdx.x;
    const int b = row >> 9, i = row & 511;
    const size_t base = (size_t)row * L_;
    float v = g_WA[base + t];
    __shared__ float red[512];
    red[t] = v; __syncthreads();
    for (int st = 256; st > 0; st >>= 1) { if (t < st) red[t] = fmaxf(red[t], red[t + st]); __syncthreads(); }
    const float mx = red[0]; __syncthreads();
    float e = expf(v - mx) * mask[b * L_ + t];
    red[t] = e; __syncthreads();
    for (int st = 256; st > 0; st >>= 1) { if (t < st) red[t] += red[t + st]; __syncthreads(); }
    const float sum = red[0];
    float att = e / (sum + EPSF) * mask[b * L_ + i];
    g_WAh[base + t] = __float2half_rn(att + __half2float(g_A1h[base + t]));
}

// =====================================================================
extern "C" void kernel_launch(void* const* d_in, const int* in_sizes, int n_in,
                              void* d_out, int out_size)
{
    const float* aspect_in  = (const float*)d_in[0];
    const float* opinion_in = (const float*)d_in[1];
    const float* context_in = (const float*)d_in[2];
    const float* cq   = (const float*)d_in[3];
    const float* mask = (const float*)d_in[4];
    const float* pos  = (const float*)d_in[5];
    const float* Wa = (const float*)d_in[6],  *ba = (const float*)d_in[7];
    const float* Wo = (const float*)d_in[8],  *bo = (const float*)d_in[9];
    const float* Wc = (const float*)d_in[10], *bc = (const float*)d_in[11];
    const float* Wda = (const float*)d_in[12], *bda = (const float*)d_in[13];
    const float* Wdo = (const float*)d_in[14], *bdo = (const float*)d_in[15];
    const float* Wds = (const float*)d_in[16], *bds = (const float*)d_in[17];
    float* out = (float*)d_out;

    __half *ah, *oh, *ch, *cqh, *posh, *Wah, *Woh, *Wch;
    __half *aconvh, *oconvh, *cconvh, *A1h, *A2h, *Gh, *WAh;
    float *G, *WA, *inva, *invo, *invc, *colsumP, *conf, *q;
    float *P1, *P1a, *Ps, *rowpart, *colpart;
    cudaGetSymbolAddress((void**)&ah,     g_ah);
    cudaGetSymbolAddress((void**)&oh,     g_oh);
    cudaGetSymbolAddress((void**)&ch,     g_ch);
    cudaGetSymbolAddress((void**)&cqh,    g_cqh);
    cudaGetSymbolAddress((void**)&posh,   g_posh);
    cudaGetSymbolAddress((void**)&Wah,    g_Wah);
    cudaGetSymbolAddress((void**)&Woh,    g_Woh);
    cudaGetSymbolAddress((void**)&Wch,    g_Wch);
    cudaGetSymbolAddress((void**)&aconvh, g_aconvh);
    cudaGetSymbolAddress((void**)&oconvh, g_oconvh);
    cudaGetSymbolAddress((void**)&cconvh, g_cconvh);
    cudaGetSymbolAddress((void**)&A1h,    g_A1h);
    cudaGetSymbolAddress((void**)&A2h,    g_A2h);
    cudaGetSymbolAddress((void**)&Gh,     g_Gh);
    cudaGetSymbolAddress((void**)&WAh,    g_WAh);
    cudaGetSymbolAddress((void**)&G,      g_G);
    cudaGetSymbolAddress((void**)&WA,     g_WA);
    cudaGetSymbolAddress((void**)&inva,   g_inva);
    cudaGetSymbolAddress((void**)&invo,   g_invo);
    cudaGetSymbolAddress((void**)&invc,   g_invc);
    cudaGetSymbolAddress((void**)&colsumP,g_colsumP);
    cudaGetSymbolAddress((void**)&conf,   g_conf);
    cudaGetSymbolAddress((void**)&q,      g_q);
    cudaGetSymbolAddress((void**)&P1,     g_P1);
    cudaGetSymbolAddress((void**)&P1a,    g_P1a);
    cudaGetSymbolAddress((void**)&Ps,     g_Ps);
    cudaGetSymbolAddress((void**)&rowpart,g_rowpart);
    cudaGetSymbolAddress((void**)&colpart,g_colpart);
    __half* eGh = reinterpret_cast<__half*>(G);

    cudaFuncSetAttribute(tc_gemm<true, true>,   cudaFuncAttributeMaxDynamicSharedMemorySize, SMEM_DYN);
    cudaFuncSetAttribute(tc_gemm<false, true>,  cudaFuncAttributeMaxDynamicSharedMemorySize, SMEM_DYN);
    cudaFuncSetAttribute(tc_gemm<false, false>, cudaFuncAttributeMaxDynamicSharedMemorySize, SMEM_DYN);

    static cudaStream_t s1 = nullptr, s2 = nullptr;
    static cudaEvent_t ev[12] = {};
    if (!s1) {
        cudaStreamCreateWithFlags(&s1, cudaStreamNonBlocking);
        cudaStreamCreateWithFlags(&s2, cudaStreamNonBlocking);
        for (int i = 0; i < 12; i++) cudaEventCreateWithFlags(&ev[i], cudaEventDisableTiming);
    }
    cudaEvent_t evRoot = ev[0], evPos = ev[1], ev1 = ev[2], ev2 = ev[3],
                evA12 = ev[4], evConf = ev[5], evE1 = ev[6], evC2 = ev[7],
                evP1a = ev[8], evSmax = ev[9];

    // ---- FORK ----
    cudaEventRecord(evRoot, 0);
    cudaStreamWaitEvent(s1, evRoot, 0);
    cudaStreamWaitEvent(s2, evRoot, 0);

    const int nIN = M_ * E_ / 4, nPOS = B_ * L_ * L_ / 4;

    // default: aspect path
    cvt_k<<<(nIN + 255) / 256, 256>>>((const float4*)aspect_in, (uint2*)ah, nIN);
    cvt_k<<<(2304 * 512 / 4 + 255) / 256, 256>>>((const float4*)Wa, (uint2*)Wah, 2304 * 512 / 4);
    tc_gemm<true, true><<<dim3(128, 4, 1), 256, SMEM_DYN>>>(
        ah, 0, Wah, 0, 512, 2304, out + OFF_AINT, 0, 1024, ba,
        nullptr, nullptr, nullptr, nullptr, nullptr, nullptr, 0, aconvh, 0, 512, 0,
        nullptr, nullptr, nullptr);
    rowinv_h<<<M_, 256>>>(aconvh, 512, inva);

    // s1: opinion path, P1a, then pos/cq conversions
    cvt_k<<<(2304 * 512 / 4 + 255) / 256, 256, 0, s1>>>((const float4*)Wo, (uint2*)Woh, 2304 * 512 / 4);
    cvt_k<<<(nIN + 255) / 256, 256, 0, s1>>>((const float4*)opinion_in, (uint2*)oh, nIN);
    tc_gemm<true, true><<<dim3(128, 4, 1), 256, SMEM_DYN, s1>>>(
        oh, 0, Woh, 0, 512, 2304, out + OFF_OINT, 0, 1024, bo,
        nullptr, nullptr, nullptr, nullptr, nullptr, nullptr, 0, oconvh, 0, 512, 0,
        nullptr, nullptr, nullptr);
    rowinv_h<<<M_, 256, 0, s1>>>(oconvh, 512, invo);
    cudaEventRecord(ev1, s1);
    pk_k<<<M_, 128, 0, s1>>>(oconvh, 512, Wda + 512 * 3, P1a);
    cudaEventRecord(evP1a, s1);
    cvt_k<<<(nPOS + 255) / 256, 256, 0, s1>>>((const float4*)pos, (uint2*)posh, nPOS);
    cvt_k<<<(nIN + 255) / 256, 256, 0, s1>>>((const float4*)cq, (uint2*)cqh, nIN);
    cudaEventRecord(evPos, s1);

    // s2: context path + Ps
    cvt_k<<<(2304 * 768 / 4 + 255) / 256, 256, 0, s2>>>((const float4*)Wc, (uint2*)Wch, 2304 * 768 / 4);
    cvt_k<<<(nIN + 255) / 256, 256, 0, s2>>>((const float4*)context_in, (uint2*)ch, nIN);
    tc_gemm<true, true><<<dim3(128, 6, 1), 256, SMEM_DYN, s2>>>(
        ch, 0, Wch, 0, 768, 2304, out + OFF_CCONV, 0, 768, bc,
        nullptr, nullptr, nullptr, nullptr, nullptr, nullptr, 0, cconvh, 0, 768, 0,
        nullptr, nullptr, nullptr);
    rowinv_h<<<M_, 256, 0, s2>>>(cconvh, 768, invc);
    cudaEventRecord(ev2, s2);
    pk_k<<<M_, 128, 0, s2>>>(cconvh, 768, Wds, Ps);

    // ---- chain A (default): gram (fused exp + row/col partials) -> a12 -> apred -> A1 GEMM
    cudaStreamWaitEvent(0, ev1, 0);
    tc_gemm<false, false><<<dim3(4, 4, B_), 256, SMEM_DYN>>>(
        aconvh, 512LL * 512, oconvh, 512LL * 512, 512, 512, nullptr, 0, 512,
        nullptr, inva, invo, nullptr, nullptr, nullptr, nullptr, 0, eGh, 512LL * 512, 512, 1,
        mask, rowpart, colpart);
    a12_k<<<dim3(16, 16, B_), dim3(32, 32)>>>(mask);
    cudaEventRecord(evA12, 0);
    cudaStreamWaitEvent(0, evP1a, 0);
    xpred_k<<<M_, 128>>>(aconvh, A1h, Wda, P1a, bda, out + OFF_APRED, nullptr);
    tc_gemm<false, true><<<dim3(4, 4, B_), 256, SMEM_DYN>>>(
        A1h, 512LL * 512, oconvh, 512LL * 512, 512, 512, out + OFF_AINT + 512, 512LL * 1024, 1024,
        nullptr, nullptr, nullptr, nullptr, nullptr, nullptr, nullptr, 0, nullptr, 0, 0, 0,
        nullptr, nullptr, nullptr);

    // ---- chain B (s1): context-attention front (R14 form)
    cudaStreamWaitEvent(s1, ev2, 0);
    tc_gemm<false, false><<<dim3(4, 4, B_), 256, SMEM_DYN, s1>>>(
        cqh, 512LL * 768, cconvh, 512LL * 768, 768, 768, nullptr, 0, 512,
        nullptr, nullptr, invc, nullptr, nullptr, nullptr, nullptr, 0, Gh, 512LL * 512, 512, 0,
        nullptr, nullptr, nullptr);
    tc_gemm<false, true><<<dim3(4, 4, B_), 256, SMEM_DYN, s1>>>(
        Gh, 512LL * 512, posh, 512LL * 512, 512, 512, WA, 512LL * 512, 512,
        nullptr, nullptr, nullptr, nullptr, nullptr, nullptr, nullptr, 0, nullptr, 0, 0, 0,
        nullptr, nullptr, nullptr);
    cudaStreamWaitEvent(s1, evA12, 0);
    smax_combine_k<<<M_, 512, 0, s1>>>(mask);
    cudaEventRecord(evSmax, s1);

    // ---- chain C (s2): propagation pieces, fast conf, spred, A2 GEMM
    cudaStreamWaitEvent(s2, evPos, 0);
    colsum_hk<<<dim3(B_, 4), 128, 0, s2>>>(posh, colsumP);
    msum_k<<<B_, 512, 0, s2>>>(mask);
    qprop_k<<<dim3(B_, 6), 128, 0, s2>>>(cconvh);
    qs_k<<<B_, 128, 0, s2>>>(Wds);
    cudaStreamWaitEvent(s2, evA12, 0);
    pk_k<<<M_, 128, 0, s2>>>(aconvh, 512, Wdo + 512 * 3, P1);
    xpred_k<<<M_, 128, 0, s2>>>(oconvh, A2h, Wdo, P1, bdo, out + OFF_OPRED, conf);
    cudaEventRecord(evConf, s2);
    cudaStreamWaitEvent(s2, evSmax, 0);
    spred_k<<<M_, 128, 0, s2>>>(cq, Wds, bds, out + OFF_SPRED);
    tc_gemm<false, true><<<dim3(4, 4, B_), 256, SMEM_DYN, s2>>>(
        A2h, 512LL * 512, aconvh, 512LL * 512, 512, 512, out + OFF_OINT + 512, 512LL * 1024, 1024,
        nullptr, nullptr, nullptr, nullptr, nullptr, nullptr, nullptr, 0, nullptr, 0, 0, 0,
        nullptr, nullptr, nullptr);
    cudaEventRecord(evC2, s2);

    // ---- s1 tail: final context GEMM (writes CINT output)
    cudaStreamWaitEvent(s1, evConf, 0);
    tc_gemm<false, true><<<dim3(4, 6, B_), 256, SMEM_DYN, s1>>>(
        WAh, 512LL * 512, cconvh, 512LL * 768, 768, 512, out + OFF_CINT, 512LL * 768, 768,
        nullptr, nullptr, nullptr, cq, conf, q, nullptr, 0, nullptr, 0, 0, 0,
        nullptr, nullptr, nullptr);
    cudaEventRecord(evE1, s1);

    // ---- join ----
    cudaStreamWaitEvent(0, evE1, 0);
    cudaStreamWaitEvent(0, evC2, 0);
}

// round 17
// speedup vs baseline: 1.0898x; 1.0842x over previous
#include <cuda_runtime.h>
#include <cuda_fp16.h>
#include <cstdint>
#include <cstddef>

#define B_  32
#define L_  512
#define E_  768
#define F_  512
#define M_  (B_ * L_)
#define EPSF 1e-7f

#define OFF_APRED 0L
#define OFF_OPRED 49152L
#define OFF_SPRED 98304L
#define OFF_AINT  147456L
#define OFF_OINT  16924672L
#define OFF_CINT  33701888L
#define OFF_CCONV 46284800L

__device__ __half g_ah  [(size_t)M_ * E_];
__device__ __half g_oh  [(size_t)M_ * E_];
__device__ __half g_ch  [(size_t)M_ * E_];
__device__ __half g_cqh [(size_t)M_ * E_];
__device__ __half g_posh[(size_t)B_ * L_ * L_];
__device__ __half g_Wah [2304 * 512];
__device__ __half g_Woh [2304 * 512];
__device__ __half g_Wch [2304 * 768];
__device__ __half g_aconvh[(size_t)M_ * F_];
__device__ __half g_oconvh[(size_t)M_ * F_];
__device__ __half g_cconvh[(size_t)M_ * E_];
__device__ __half g_A1h[(size_t)B_ * L_ * L_];
__device__ __half g_A2h[(size_t)B_ * L_ * L_];
__device__ __half g_Gh [(size_t)B_ * L_ * L_];
__device__ __half g_WAh[(size_t)B_ * L_ * L_];
__device__ float g_G [(size_t)B_ * L_ * L_];   // first half reused as fp16 expG
__device__ float g_WA[(size_t)B_ * L_ * L_];
__device__ float g_inva[M_], g_invo[M_], g_invc[M_];
__device__ float g_rowsum[M_], g_colsum[M_], g_colsumP[M_];
__device__ float g_msum[B_];
__device__ float g_conf[M_];
__device__ float g_q[(size_t)B_ * E_];
__device__ float g_P1 [(size_t)M_ * 3];
__device__ float g_P1a[(size_t)M_ * 3];
__device__ float g_Ps [(size_t)M_ * 3];
__device__ float g_qs [B_ * 3];

// ---------------- helpers ----------------
__device__ __forceinline__ uint32_t su32(const void* p) {
    uint32_t a;
    asm("{ .reg .u64 t; cvta.to.shared.u64 t, %1; cvt.u32.u64 %0, t; }" : "=r"(a) : "l"(p));
    return a;
}
__device__ __forceinline__ void ldm_x4(uint32_t* r, uint32_t addr) {
    asm volatile("ldmatrix.sync.aligned.m8n8.x4.shared.b16 {%0,%1,%2,%3}, [%4];"
                 : "=r"(r[0]), "=r"(r[1]), "=r"(r[2]), "=r"(r[3]) : "r"(addr));
}
__device__ __forceinline__ void ldm_x4t(uint32_t* r, uint32_t addr) {
    asm volatile("ldmatrix.sync.aligned.m8n8.x4.trans.shared.b16 {%0,%1,%2,%3}, [%4];"
                 : "=r"(r[0]), "=r"(r[1]), "=r"(r[2]), "=r"(r[3]) : "r"(addr));
}
__device__ __forceinline__ void mma_f16(float* c, const uint32_t* a, const uint32_t* b) {
    asm volatile(
        "mma.sync.aligned.m16n8k16.row.col.f32.f16.f16.f32 "
        "{%0,%1,%2,%3}, {%4,%5,%6,%7}, {%8,%9}, {%0,%1,%2,%3};"
        : "+f"(c[0]), "+f"(c[1]), "+f"(c[2]), "+f"(c[3])
        : "r"(a[0]), "r"(a[1]), "r"(a[2]), "r"(a[3]), "r"(b[0]), "r"(b[1]));
}
__device__ __forceinline__ uint32_t pkh(float x, float y) {
    __half2 t = __floats2half2_rn(x, y);
    return *reinterpret_cast<uint32_t*>(&t);
}

// ---------------- fp16 tensor-core GEMM, BK=64, one barrier/chunk ----------------
#define AROWB 144
#define NROWB 272
#define S_B   18432
#define STAGE 36864
#define SMEM_DYN (2 * STAGE)

template<bool GATHER, bool BNN>
__global__ __launch_bounds__(256, 2)
void tc_gemm(const __half* __restrict__ A, long long ab,
             const __half* __restrict__ Bm, long long bb, int ldb, int K,
             float* __restrict__ C, long long cb, int ldc,
             const float* __restrict__ bias,
             const float* __restrict__ rs, const float* __restrict__ cs,
             const float* __restrict__ addp,
             const float* __restrict__ rowv, const float* __restrict__ colv,
             float* __restrict__ C2, int ldc2,
             __half* __restrict__ Ch, long long cbh, int ldch,
             int doexp)
{
    extern __shared__ char smem[];
    const int tid = threadIdx.x;
    const int lane = tid & 31, wid = tid >> 5;
    const int wm = wid & 3, wn = wid >> 2;
    const int m0 = blockIdx.x * 128, n0 = blockIdx.y * 128, bz = blockIdx.z;
    const uint32_t sb0 = su32(smem);

    const __half* Ab = GATHER ? A : (A + (size_t)bz * ab);
    const __half* Bb = Bm + (size_t)bz * bb;

    float c[2][8][4];
#pragma unroll
    for (int i = 0; i < 2; i++)
#pragma unroll
        for (int j = 0; j < 8; j++)
#pragma unroll
            for (int k = 0; k < 4; k++) c[i][j][k] = 0.f;

    const int nch = K / 64;
    uint4 va[4], vb[4];

    auto ldg = [&](int kc) {
        const int k0 = kc * 64;
#pragma unroll
        for (int p = 0; p < 4; p++) {
            const int idx = tid + p * 256, row = idx >> 3, c16 = idx & 7;
            if (GATHER) {
                const int gm = m0 + row, b = gm >> 9, l = gm & 511;
                const int tap = kc / 12, e0 = (kc - tap * 12) * 64;
                const int src = l + tap - 1;
                va[p] = ((unsigned)src < 512u)
                    ? *reinterpret_cast<const uint4*>(A + ((size_t)(b * 512 + src)) * 768 + e0 + c16 * 8)
                    : make_uint4(0u, 0u, 0u, 0u);
            } else {
                va[p] = *reinterpret_cast<const uint4*>(Ab + (size_t)(m0 + row) * K + k0 + c16 * 8);
            }
        }
        if (BNN) {
#pragma unroll
            for (int p = 0; p < 4; p++) {
                const int idx = tid + p * 256, kr = idx >> 4, c16 = idx & 15;
                vb[p] = *reinterpret_cast<const uint4*>(Bb + (size_t)(k0 + kr) * ldb + n0 + c16 * 8);
            }
        } else {
#pragma unroll
            for (int p = 0; p < 4; p++) {
                const int idx = tid + p * 256, row = idx >> 3, c16 = idx & 7;
                vb[p] = *reinterpret_cast<const uint4*>(Bb + (size_t)(n0 + row) * ldb + k0 + c16 * 8);
            }
        }
    };
    auto sts = [&](int s) {
        char* sp = smem + s * STAGE;
#pragma unroll
        for (int p = 0; p < 4; p++) {
            const int idx = tid + p * 256, row = idx >> 3, c16 = idx & 7;
            *reinterpret_cast<uint4*>(sp + row * AROWB + c16 * 16) = va[p];
        }
        if (BNN) {
#pragma unroll
            for (int p = 0; p < 4; p++) {
                const int idx = tid + p * 256, kr = idx >> 4, c16 = idx & 15;
                *reinterpret_cast<uint4*>(sp + S_B + kr * NROWB + c16 * 16) = vb[p];
            }
        } else {
#pragma unroll
            for (int p = 0; p < 4; p++) {
                const int idx = tid + p * 256, row = idx >> 3, c16 = idx & 7;
                *reinterpret_cast<uint4*>(sp + S_B + row * AROWB + c16 * 16) = vb[p];
            }
        }
    };

    const uint32_t a_lrow = (lane & 15), a_lcol = (lane >> 4) * 8;
    const uint32_t nt_lrow = (lane & 7) + ((lane >> 4) << 3), nt_lcol = ((lane >> 3) & 1) * 8;
    const uint32_t nn_krow = (lane & 7) + (((lane >> 3) & 1) << 3), nn_ncol = (lane >> 4) * 8;

    auto compute = [&](int s) {
        const uint32_t base = sb0 + s * STAGE;
#pragma unroll
        for (int ks = 0; ks < 4; ks++) {
            const int kk = ks * 16;
            uint32_t af[2][4];
#pragma unroll
            for (int mf = 0; mf < 2; mf++)
                ldm_x4(af[mf], base + (wm * 32 + mf * 16 + a_lrow) * AROWB + (kk + a_lcol) * 2);
#pragma unroll
            for (int nf2 = 0; nf2 < 4; nf2++) {
                uint32_t bt[4];
                if (BNN)
                    ldm_x4t(bt, base + S_B + (kk + nn_krow) * NROWB + (wn * 64 + nf2 * 16 + nn_ncol) * 2);
                else
                    ldm_x4(bt, base + S_B + (wn * 64 + nf2 * 16 + nt_lrow) * AROWB + (kk + nt_lcol) * 2);
#pragma unroll
                for (int mf = 0; mf < 2; mf++) {
                    mma_f16(c[mf][nf2 * 2 + 0], af[mf], bt);
                    mma_f16(c[mf][nf2 * 2 + 1], af[mf], bt + 2);
                }
            }
        }
    };

    ldg(0);
    sts(0);
    ldg(1);
    __syncthreads();
    for (int i = 0; i < nch; i++) {
        if (i + 1 < nch) sts((i + 1) & 1);
        if (i + 2 < nch) ldg(i + 2);
        compute(i & 1);
        __syncthreads();
    }

    const int tm = lane >> 2, tn = (lane & 3) * 2;
#pragma unroll
    for (int mf = 0; mf < 2; mf++) {
#pragma unroll
        for (int nf = 0; nf < 8; nf++) {
#pragma unroll
            for (int half = 0; half < 2; half++) {
                const int m = m0 + wm * 32 + mf * 16 + tm + half * 8;
                const int nn = n0 + wn * 64 + nf * 8 + tn;
                float v0 = c[mf][nf][half * 2 + 0];
                float v1 = c[mf][nf][half * 2 + 1];
                if (rs) { const float r = rs[bz * 512 + m]; v0 *= r; v1 *= r; }
                if (cs) { v0 *= cs[bz * 512 + nn]; v1 *= cs[bz * 512 + nn + 1]; }
                if (doexp) { v0 = expf(v0); v1 = expf(v1); }
                if (bias) {
                    v0 = fmaxf(v0 + bias[nn], 0.f);
                    v1 = fmaxf(v1 + bias[nn + 1], 0.f);
                }
                if (C) {
                    const size_t rowoff = (size_t)bz * cb + (size_t)m * ldc + nn;
                    if (addp) { v0 += addp[rowoff]; v1 += addp[rowoff + 1]; }
                    if (rowv) {
                        const float rv = rowv[bz * 512 + m];
                        v0 += rv * colv[(size_t)bz * ldc + nn];
                        v1 += rv * colv[(size_t)bz * ldc + nn + 1];
                    }
                    C[rowoff] = v0; C[rowoff + 1] = v1;
                }
                if (C2) {
                    float* c2 = C2 + (size_t)m * ldc2 + nn;
                    c2[0] = v0; c2[1] = v1;
                }
                if (Ch) {
                    *reinterpret_cast<__half2*>(Ch + (size_t)bz * cbh + (size_t)m * ldch + nn) =
                        __floats2half2_rn(v0, v1);
                }
            }
        }
    }
}

// ---------------- small kernels ----------------
__global__ void cvt_k(const float4* __restrict__ src, uint2* __restrict__ dst, int n4)
{
    const int i = blockIdx.x * 256 + threadIdx.x;
    if (i < n4) {
        float4 v = src[i];
        dst[i] = make_uint2(pkh(v.x, v.y), pkh(v.z, v.w));
    }
}
// warp-per-row inverse l2 norm (8 rows per 256-thread block)
__global__ void rowinv_w(const __half* __restrict__ X, int D, float* __restrict__ inv)
{
    const int w = threadIdx.x >> 5, lane = threadIdx.x & 31;
    const int m = blockIdx.x * 8 + w;
    const __half2* xr = reinterpret_cast<const __half2*>(X + (size_t)m * D);
    float s = 0.f;
    for (int k = lane; k < D / 2; k += 32) {
        float2 v = __half22float2(xr[k]);
        s = fmaf(v.x, v.x, fmaf(v.y, v.y, s));
    }
#pragma unroll
    for (int o = 16; o > 0; o >>= 1) s += __shfl_down_sync(0xffffffffu, s, o);
    if (lane == 0) inv[m] = rsqrtf(fmaxf(s, 1e-12f));
}
// combined masked rowsum (blocks 0..M_-1) + masked colsum (blocks M_..M_+B_-1) of fp16 expG
__global__ void sums_k(const float* __restrict__ mask)
{
    const __half* eG = reinterpret_cast<const __half*>(g_G);
    const int t = threadIdx.x;   // 512 threads
    if (blockIdx.x < M_) {
        const int row = blockIdx.x;
        const int b = row >> 9;
        float v = __half2float(eG[(size_t)row * L_ + t]) * mask[b * L_ + t];
        __shared__ float red[512];
        red[t] = v; __syncthreads();
        for (int st = 256; st > 0; st >>= 1) { if (t < st) red[t] += red[t + st]; __syncthreads(); }
        if (t == 0) g_rowsum[row] = red[0];
    } else {
        const int b = blockIdx.x - M_;
        const __half* S = eG + (size_t)b * L_ * L_;
        float acc = 0.f;
#pragma unroll 4
        for (int r = 0; r < L_; r++)
            acc = fmaf(__half2float(S[(size_t)r * L_ + t]), mask[b * L_ + r], acc);
        g_colsum[b * L_ + t] = acc;
    }
}
__global__ void colsum_hk(const __half* __restrict__ src, float* __restrict__ dst)
{
    const int b = blockIdx.x, c = blockIdx.y * 128 + threadIdx.x;
    const __half* S = src + (size_t)b * L_ * L_;
    float acc = 0.f;
#pragma unroll 4
    for (int r = 0; r < L_; r++)
        acc += __half2float(S[(size_t)r * L_ + c]);
    dst[b * L_ + c] = acc;
}
__global__ void qprop_k(const __half* __restrict__ cconvh)
{
    const int b = blockIdx.x, e = blockIdx.y * 128 + threadIdx.x;
    float acc = 0.f;
#pragma unroll 4
    for (int r = 0; r < L_; r++)
        acc = fmaf(g_colsumP[b * L_ + r],
                   __half2float(cconvh[((size_t)(b * L_ + r)) * E_ + e]), acc);
    g_q[b * E_ + e] = acc * g_msum[b];
}
__global__ void a12_k(const float* __restrict__ mask)
{
    const __half* eG = reinterpret_cast<const __half*>(g_G);
    __shared__ float s[32][33];
    const int b = blockIdx.z;
    const int i0 = blockIdx.y * 32, j0 = blockIdx.x * 32;
    const int tx = threadIdx.x, ty = threadIdx.y;
    const __half* Eb = eG + (size_t)b * L_ * L_;
    const float* mk = mask + b * L_;
    s[ty][tx] = __half2float(Eb[(size_t)(i0 + ty) * L_ + j0 + tx]);
    __syncthreads();
    float a1 = s[ty][tx] * mk[j0 + tx] / (g_rowsum[b * L_ + i0 + ty] + EPSF) * mk[i0 + ty];
    g_A1h[(size_t)b * L_ * L_ + (size_t)(i0 + ty) * L_ + j0 + tx] = __float2half_rn(a1);
    float a2 = s[tx][ty] * mk[i0 + tx] / (g_colsum[b * L_ + j0 + ty] + EPSF) * mk[j0 + ty];
    g_A2h[(size_t)b * L_ * L_ + (size_t)(j0 + ty) * L_ + i0 + tx] = __float2half_rn(a2);
}
__device__ __forceinline__ void red3(float& a0, float& a1, float& a2, int t)
{
#pragma unroll
    for (int o = 16; o > 0; o >>= 1) {
        a0 += __shfl_down_sync(0xffffffffu, a0, o);
        a1 += __shfl_down_sync(0xffffffffu, a1, o);
        a2 += __shfl_down_sync(0xffffffffu, a2, o);
    }
    __shared__ float sh[4][3];
    const int w = t >> 5, ln = t & 31;
    if (ln == 0) { sh[w][0] = a0; sh[w][1] = a1; sh[w][2] = a2; }
    __syncthreads();
    if (t == 0) {
        a0 = sh[0][0] + sh[1][0] + sh[2][0] + sh[3][0];
        a1 = sh[0][1] + sh[1][1] + sh[2][1] + sh[3][1];
        a2 = sh[0][2] + sh[1][2] + sh[2][2] + sh[3][2];
    }
}
__global__ void pk_k(const __half* __restrict__ Xh, int D,
                     const float* __restrict__ Wd, float* __restrict__ out)
{
    const int m = blockIdx.x, t = threadIdx.x;
    const __half2* xr = reinterpret_cast<const __half2*>(Xh + (size_t)m * D);
    float a0 = 0.f, a1 = 0.f, a2 = 0.f;
    for (int k2 = t; k2 < D / 2; k2 += 128) {
        float2 x = __half22float2(xr[k2]);
        const float* w = Wd + (size_t)(k2 * 2) * 3;
        a0 = fmaf(x.x, w[0], a0); a1 = fmaf(x.x, w[1], a1); a2 = fmaf(x.x, w[2], a2);
        a0 = fmaf(x.y, w[3], a0); a1 = fmaf(x.y, w[4], a1); a2 = fmaf(x.y, w[5], a2);
    }
    red3(a0, a1, a2, t);
    if (t == 0) {
        out[(size_t)m * 3 + 0] = a0;
        out[(size_t)m * 3 + 1] = a1;
        out[(size_t)m * 3 + 2] = a2;
    }
}
__global__ void xpred_k(const __half* __restrict__ Xh, const __half* __restrict__ Ah,
                        const float* __restrict__ Wd, const float* __restrict__ P,
                        const float* __restrict__ bd,
                        float* __restrict__ out, float* __restrict__ conf)
{
    const int m = blockIdx.x, t = threadIdx.x;
    const int b = m >> 9;
    float a0 = 0.f, a1 = 0.f, a2 = 0.f;
    const __half2* xr = reinterpret_cast<const __half2*>(Xh + (size_t)m * 512);
    for (int k2 = t; k2 < 256; k2 += 128) {
        float2 x = __half22float2(xr[k2]);
        const float* w = Wd + (size_t)(k2 * 2) * 3;
        a0 = fmaf(x.x, w[0], a0); a1 = fmaf(x.x, w[1], a1); a2 = fmaf(x.x, w[2], a2);
        a0 = fmaf(x.y, w[3], a0); a1 = fmaf(x.y, w[4], a1); a2 = fmaf(x.y, w[5], a2);
    }
    const __half2* ar = reinterpret_cast<const __half2*>(Ah + (size_t)m * 512);
    const float* Pb = P + (size_t)b * 512 * 3;
    for (int k2 = t; k2 < 256; k2 += 128) {
        float2 x = __half22float2(ar[k2]);
        const float* p = Pb + (size_t)(k2 * 2) * 3;
        a0 = fmaf(x.x, p[0], a0); a1 = fmaf(x.x, p[1], a1); a2 = fmaf(x.x, p[2], a2);
        a0 = fmaf(x.y, p[3], a0); a1 = fmaf(x.y, p[4], a1); a2 = fmaf(x.y, p[5], a2);
    }
    red3(a0, a1, a2, t);
    if (t == 0) {
        float p0 = a0 + bd[0], p1 = a1 + bd[1], p2 = a2 + bd[2];
        out[(size_t)m * 3 + 0] = p0;
        out[(size_t)m * 3 + 1] = p1;
        out[(size_t)m * 3 + 2] = p2;
        if (conf) {
            float mx = fmaxf(p0, fmaxf(p1, p2));
            float e0 = expf(p0 - mx), e1 = expf(p1 - mx), e2 = expf(p2 - mx);
            conf[m] = fmaxf(0.f, 1.f - 2.f * e0 / (e0 + e1 + e2));
        }
    }
}
__global__ void qs_k(const float* __restrict__ Wd)
{
    const int b = blockIdx.x, t = threadIdx.x;
    float a0 = 0.f, a1 = 0.f, a2 = 0.f;
    for (int k = t; k < 768; k += 128) {
        float x = g_q[b * 768 + k];
        const float* w = Wd + (size_t)k * 3;
        a0 = fmaf(x, w[0], a0); a1 = fmaf(x, w[1], a1); a2 = fmaf(x, w[2], a2);
    }
    red3(a0, a1, a2, t);
    if (t == 0) { g_qs[b * 3] = a0; g_qs[b * 3 + 1] = a1; g_qs[b * 3 + 2] = a2; }
}
__global__ void spred_k(const float* __restrict__ cq, const float* __restrict__ Wd,
                        const float* __restrict__ bd, float* __restrict__ out)
{
    const int m = blockIdx.x, t = threadIdx.x;
    const int b = m >> 9;
    float a0 = 0.f, a1 = 0.f, a2 = 0.f;
    const float* xr = cq + (size_t)m * 768;
    for (int k = t; k < 768; k += 128) {
        float x = xr[k];
        const float* w = Wd + (size_t)k * 3;
        a0 = fmaf(x, w[0], a0); a1 = fmaf(x, w[1], a1); a2 = fmaf(x, w[2], a2);
    }
    const __half2* ar = reinterpret_cast<const __half2*>(g_WAh + (size_t)m * 512);
    const float* Pb = g_Ps + (size_t)b * 512 * 3;
    for (int k2 = t; k2 < 256; k2 += 128) {
        float2 x = __half22float2(ar[k2]);
        const float* p = Pb + (size_t)(k2 * 2) * 3;
        a0 = fmaf(x.x, p[0], a0); a1 = fmaf(x.x, p[1], a1); a2 = fmaf(x.x, p[2], a2);
        a0 = fmaf(x.y, p[3], a0); a1 = fmaf(x.y, p[4], a1); a2 = fmaf(x.y, p[5], a2);
    }
    red3(a0, a1, a2, t);
    if (t == 0) {
        const float cf = g_conf[m];
        out[(size_t)m * 3 + 0] = a0 + bd[0] + cf * g_qs[b * 3 + 0];
        out[(size_t)m * 3 + 1] = a1 + bd[1] + cf * g_qs[b * 3 + 1];
        out[(size_t)m * 3 + 2] = a2 + bd[2] + cf * g_qs[b * 3 + 2];
    }
}
__global__ void msum_k(const float* __restrict__ mask)
{
    const int b = blockIdx.x, t = threadIdx.x;
    __shared__ float red[512];
    red[t] = mask[b * L_ + t]; __syncthreads();
    for (int st = 256; st > 0; st >>= 1) { if (t < st) red[t] += red[t + st]; __syncthreads(); }
    if (t == 0) g_msum[b] = red[0];
}
__global__ void smax_combine_k(const float* __restrict__ mask)
{
    const int row = blockIdx.x, t = threadIdx.x;
    const int b = row >> 9, i = row & 511;
    const size_t base = (size_t)row * L_;
    float v = g_WA[base + t];
    __shared__ float red[512];
    red[t] = v; __syncthreads();
    for (int st = 256; st > 0; st >>= 1) { if (t < st) red[t] = fmaxf(red[t], red[t + st]); __syncthreads(); }
    const float mx = red[0]; __syncthreads();
    float e = expf(v - mx) * mask[b * L_ + t];
    red[t] = e; __syncthreads();
    for (int st = 256; st > 0; st >>= 1) { if (t < st) red[t] += red[t + st]; __syncthreads(); }
    const float sum = red[0];
    float att = e / (sum + EPSF) * mask[b * L_ + i];
    g_WAh[base + t] = __float2half_rn(att + __half2float(g_A1h[base + t]));
}

// =====================================================================
extern "C" void kernel_launch(void* const* d_in, const int* in_sizes, int n_in,
                              void* d_out, int out_size)
{
    const float* aspect_in  = (const float*)d_in[0];
    const float* opinion_in = (const float*)d_in[1];
    const float* context_in = (const float*)d_in[2];
    const float* cq   = (const float*)d_in[3];
    const float* mask = (const float*)d_in[4];
    const float* pos  = (const float*)d_in[5];
    const float* Wa = (const float*)d_in[6],  *ba = (const float*)d_in[7];
    const float* Wo = (const float*)d_in[8],  *bo = (const float*)d_in[9];
    const float* Wc = (const float*)d_in[10], *bc = (const float*)d_in[11];
    const float* Wda = (const float*)d_in[12], *bda = (const float*)d_in[13];
    const float* Wdo = (const float*)d_in[14], *bdo = (const float*)d_in[15];
    const float* Wds = (const float*)d_in[16], *bds = (const float*)d_in[17];
    float* out = (float*)d_out;

    __half *ah, *oh, *ch, *cqh, *posh, *Wah, *Woh, *Wch;
    __half *aconvh, *oconvh, *cconvh, *A1h, *A2h, *Gh, *WAh;
    float *G, *WA, *inva, *invo, *invc, *colsumP, *conf, *q;
    float *P1, *P1a, *Ps;
    cudaGetSymbolAddress((void**)&ah,     g_ah);
    cudaGetSymbolAddress((void**)&oh,     g_oh);
    cudaGetSymbolAddress((void**)&ch,     g_ch);
    cudaGetSymbolAddress((void**)&cqh,    g_cqh);
    cudaGetSymbolAddress((void**)&posh,   g_posh);
    cudaGetSymbolAddress((void**)&Wah,    g_Wah);
    cudaGetSymbolAddress((void**)&Woh,    g_Woh);
    cudaGetSymbolAddress((void**)&Wch,    g_Wch);
    cudaGetSymbolAddress((void**)&aconvh, g_aconvh);
    cudaGetSymbolAddress((void**)&oconvh, g_oconvh);
    cudaGetSymbolAddress((void**)&cconvh, g_cconvh);
    cudaGetSymbolAddress((void**)&A1h,    g_A1h);
    cudaGetSymbolAddress((void**)&A2h,    g_A2h);
    cudaGetSymbolAddress((void**)&Gh,     g_Gh);
    cudaGetSymbolAddress((void**)&WAh,    g_WAh);
    cudaGetSymbolAddress((void**)&G,      g_G);
    cudaGetSymbolAddress((void**)&WA,     g_WA);
    cudaGetSymbolAddress((void**)&inva,   g_inva);
    cudaGetSymbolAddress((void**)&invo,   g_invo);
    cudaGetSymbolAddress((void**)&invc,   g_invc);
    cudaGetSymbolAddress((void**)&colsumP,g_colsumP);
    cudaGetSymbolAddress((void**)&conf,   g_conf);
    cudaGetSymbolAddress((void**)&q,      g_q);
    cudaGetSymbolAddress((void**)&P1,     g_P1);
    cudaGetSymbolAddress((void**)&P1a,    g_P1a);
    cudaGetSymbolAddress((void**)&Ps,     g_Ps);
    __half* eGh = reinterpret_cast<__half*>(G);

    cudaFuncSetAttribute(tc_gemm<true, true>,   cudaFuncAttributeMaxDynamicSharedMemorySize, SMEM_DYN);
    cudaFuncSetAttribute(tc_gemm<false, true>,  cudaFuncAttributeMaxDynamicSharedMemorySize, SMEM_DYN);
    cudaFuncSetAttribute(tc_gemm<false, false>, cudaFuncAttributeMaxDynamicSharedMemorySize, SMEM_DYN);

    static cudaStream_t s1 = nullptr, s2 = nullptr;
    static cudaEvent_t ev[12] = {};
    if (!s1) {
        cudaStreamCreateWithFlags(&s1, cudaStreamNonBlocking);
        cudaStreamCreateWithFlags(&s2, cudaStreamNonBlocking);
        for (int i = 0; i < 12; i++) cudaEventCreateWithFlags(&ev[i], cudaEventDisableTiming);
    }
    cudaEvent_t evRoot = ev[0], evPos = ev[1], ev1 = ev[2], ev2 = ev[3],
                evA12 = ev[4], evConf = ev[5], evE1 = ev[6], evC2 = ev[7],
                evP1a = ev[8], evSmax = ev[9];

    // ---- FORK ----
    cudaEventRecord(evRoot, 0);
    cudaStreamWaitEvent(s1, evRoot, 0);
    cudaStreamWaitEvent(s2, evRoot, 0);

    const int nIN = M_ * E_ / 4, nPOS = B_ * L_ * L_ / 4;

    // default: aspect path
    cvt_k<<<(nIN + 255) / 256, 256>>>((const float4*)aspect_in, (uint2*)ah, nIN);
    cvt_k<<<(2304 * 512 / 4 + 255) / 256, 256>>>((const float4*)Wa, (uint2*)Wah, 2304 * 512 / 4);
    tc_gemm<true, true><<<dim3(128, 4, 1), 256, SMEM_DYN>>>(
        ah, 0, Wah, 0, 512, 2304, out + OFF_AINT, 0, 1024, ba,
        nullptr, nullptr, nullptr, nullptr, nullptr, nullptr, 0, aconvh, 0, 512, 0);
    rowinv_w<<<M_ / 8, 256>>>(aconvh, 512, inva);

    // s1: opinion path, P1a, then pos/cq conversions
    cvt_k<<<(2304 * 512 / 4 + 255) / 256, 256, 0, s1>>>((const float4*)Wo, (uint2*)Woh, 2304 * 512 / 4);
    cvt_k<<<(nIN + 255) / 256, 256, 0, s1>>>((const float4*)opinion_in, (uint2*)oh, nIN);
    tc_gemm<true, true><<<dim3(128, 4, 1), 256, SMEM_DYN, s1>>>(
        oh, 0, Woh, 0, 512, 2304, out + OFF_OINT, 0, 1024, bo,
        nullptr, nullptr, nullptr, nullptr, nullptr, nullptr, 0, oconvh, 0, 512, 0);
    rowinv_w<<<M_ / 8, 256, 0, s1>>>(oconvh, 512, invo);
    cudaEventRecord(ev1, s1);
    pk_k<<<M_, 128, 0, s1>>>(oconvh, 512, Wda + 512 * 3, P1a);
    cudaEventRecord(evP1a, s1);
    cvt_k<<<(nPOS + 255) / 256, 256, 0, s1>>>((const float4*)pos, (uint2*)posh, nPOS);
    cvt_k<<<(nIN + 255) / 256, 256, 0, s1>>>((const float4*)cq, (uint2*)cqh, nIN);
    cudaEventRecord(evPos, s1);

    // s2: context path + Ps
    cvt_k<<<(2304 * 768 / 4 + 255) / 256, 256, 0, s2>>>((const float4*)Wc, (uint2*)Wch, 2304 * 768 / 4);
    cvt_k<<<(nIN + 255) / 256, 256, 0, s2>>>((const float4*)context_in, (uint2*)ch, nIN);
    tc_gemm<true, true><<<dim3(128, 6, 1), 256, SMEM_DYN, s2>>>(
        ch, 0, Wch, 0, 768, 2304, out + OFF_CCONV, 0, 768, bc,
        nullptr, nullptr, nullptr, nullptr, nullptr, nullptr, 0, cconvh, 0, 768, 0);
    rowinv_w<<<M_ / 8, 256, 0, s2>>>(cconvh, 768, invc);
    cudaEventRecord(ev2, s2);
    pk_k<<<M_, 128, 0, s2>>>(cconvh, 768, Wds, Ps);

    // ---- chain A (default): gram (fused exp) -> sums -> a12 -> apred -> A1 GEMM
    cudaStreamWaitEvent(0, ev1, 0);
    tc_gemm<false, false><<<dim3(4, 4, B_), 256, SMEM_DYN>>>(
        aconvh, 512LL * 512, oconvh, 512LL * 512, 512, 512, nullptr, 0, 512,
        nullptr, inva, invo, nullptr, nullptr, nullptr, nullptr, 0, eGh, 512LL * 512, 512, 1);
    sums_k<<<M_ + B_, 512>>>(mask);
    a12_k<<<dim3(16, 16, B_), dim3(32, 32)>>>(mask);
    cudaEventRecord(evA12, 0);
    cudaStreamWaitEvent(0, evP1a, 0);
    xpred_k<<<M_, 128>>>(aconvh, A1h, Wda, P1a, bda, out + OFF_APRED, nullptr);
    tc_gemm<false, true><<<dim3(4, 4, B_), 256, SMEM_DYN>>>(
        A1h, 512LL * 512, oconvh, 512LL * 512, 512, 512, out + OFF_AINT + 512, 512LL * 1024, 1024,
        nullptr, nullptr, nullptr, nullptr, nullptr, nullptr, nullptr, 0, nullptr, 0, 0, 0);

    // ---- chain B (s1): context-attention front
    cudaStreamWaitEvent(s1, ev2, 0);
    tc_gemm<false, false><<<dim3(4, 4, B_), 256, SMEM_DYN, s1>>>(
        cqh, 512LL * 768, cconvh, 512LL * 768, 768, 768, nullptr, 0, 512,
        nullptr, nullptr, invc, nullptr, nullptr, nullptr, nullptr, 0, Gh, 512LL * 512, 512, 0);
    tc_gemm<false, true><<<dim3(4, 4, B_), 256, SMEM_DYN, s1>>>(
        Gh, 512LL * 512, posh, 512LL * 512, 512, 512, WA, 512LL * 512, 512,
        nullptr, nullptr, nullptr, nullptr, nullptr, nullptr, nullptr, 0, nullptr, 0, 0, 0);
    cudaStreamWaitEvent(s1, evA12, 0);
    smax_combine_k<<<M_, 512, 0, s1>>>(mask);
    cudaEventRecord(evSmax, s1);

    // ---- chain C (s2): propagation pieces, fast conf, spred, A2 GEMM
    cudaStreamWaitEvent(s2, evPos, 0);
    colsum_hk<<<dim3(B_, 4), 128, 0, s2>>>(posh, colsumP);
    msum_k<<<B_, 512, 0, s2>>>(mask);
    qprop_k<<<dim3(B_, 6), 128, 0, s2>>>(cconvh);
    qs_k<<<B_, 128, 0, s2>>>(Wds);
    cudaStreamWaitEvent(s2, evA12, 0);
    pk_k<<<M_, 128, 0, s2>>>(aconvh, 512, Wdo + 512 * 3, P1);
    xpred_k<<<M_, 128, 0, s2>>>(oconvh, A2h, Wdo, P1, bdo, out + OFF_OPRED, conf);
    cudaEventRecord(evConf, s2);
    cudaStreamWaitEvent(s2, evSmax, 0);
    spred_k<<<M_, 128, 0, s2>>>(cq, Wds, bds, out + OFF_SPRED);
    tc_gemm<false, true><<<dim3(4, 4, B_), 256, SMEM_DYN, s2>>>(
        A2h, 512LL * 512, aconvh, 512LL * 512, 512, 512, out + OFF_OINT + 512, 512LL * 1024, 1024,
        nullptr, nullptr, nullptr, nullptr, nullptr, nullptr, nullptr, 0, nullptr, 0, 0, 0);
    cudaEventRecord(evC2, s2);

    // ---- s1 tail: final context GEMM (writes CINT output)
    cudaStreamWaitEvent(s1, evConf, 0);
    tc_gemm<false, true><<<dim3(4, 6, B_), 256, SMEM_DYN, s1>>>(
        WAh, 512LL * 512, cconvh, 512LL * 768, 768, 512, out + OFF_CINT, 512LL * 768, 768,
        nullptr, nullptr, nullptr, cq, conf, q, nullptr, 0, nullptr, 0, 0, 0);
    cudaEventRecord(evE1, s1);

    // ---- join ----
    cudaStreamWaitEvent(0, evE1, 0);
    cudaStreamWaitEvent(0, evC2, 0);
}